// round 12
// baseline (speedup 1.0000x reference)
#include <cuda_runtime.h>
#include <cuda_fp16.h>
#include <math.h>
#include <stdint.h>

#define DEPTH   12
#define BATCH   16
#define NTOK    256
#define TOKENS  (BATCH*NTOK)     /* 4096 */
#define DIM     768
#define HEADS   12
#define HD      64
#define HIDDEN  2048
#define EPSF    1e-5f
#define QS      2304             /* packed qkv row stride */
#define GUS     4096             /* packed g|u row stride */

/* ------------------------------------------------------------------ */
/* Scratch buffers                                                     */
/* ------------------------------------------------------------------ */
__device__ float  g_qkv[TOKENS*QS];
__device__ float  g_gu[TOKENS*GUS];
__device__ float  g_part[3*TOKENS*DIM];
__device__ __half g_oh_hi[TOKENS*DIM];
__device__ __half g_oh_lo[TOKENS*DIM];
__device__ __half g_mh_hi[TOKENS*HIDDEN];
__device__ __half g_mh_lo[TOKENS*HIDDEN];

/* int8 activation (LN output) */
__device__ char   g_yq_h[TOKENS*DIM];
__device__ char   g_yq_l[TOKENS*DIM];
__device__ float  g_say[TOKENS];

/* int8 packed weights (QKV, W1) + per-row scales */
__device__ char   g_wqkv_h[DEPTH*QS*DIM];
__device__ char   g_wqkv_l[DEPTH*QS*DIM];
__device__ float  g_sbqkv[DEPTH*QS];
__device__ char   g_w1_h[DEPTH*GUS*DIM];
__device__ char   g_w1_l[DEPTH*GUS*DIM];
__device__ float  g_sb1[DEPTH*GUS];

/* fp16 split weights (WO, W2) */
__device__ __half g_wo_hi[DEPTH*DIM*DIM];
__device__ __half g_wo_lo[DEPTH*DIM*DIM];
__device__ __half g_w2_hi[DEPTH*DIM*HIDDEN];
__device__ __half g_w2_lo[DEPTH*DIM*HIDDEN];
__device__ float  g_bqkv[DEPTH*QS];
__device__ float  g_b1[DEPTH*GUS];

/* ------------------------------------------------------------------ */
/* PTX helpers                                                         */
/* ------------------------------------------------------------------ */
__device__ __forceinline__ uint32_t smem_u32(const void* p) {
    uint32_t a;
    asm("{ .reg .u64 t; cvta.to.shared.u64 t, %1; cvt.u32.u64 %0, t; }"
        : "=r"(a) : "l"(p));
    return a;
}
__device__ __forceinline__ void cp16(uint32_t dst, const void* src) {
    asm volatile("cp.async.cg.shared.global [%0], [%1], 16;"
                 :: "r"(dst), "l"(src) : "memory");
}
__device__ __forceinline__ void cp_commit() {
    asm volatile("cp.async.commit_group;" ::: "memory");
}
template<int NWAIT>
__device__ __forceinline__ void cp_wait() {
    asm volatile("cp.async.wait_group %0;" :: "n"(NWAIT) : "memory");
}
template<int IMM>
__device__ __forceinline__ void ldmx4i(uint32_t& r0, uint32_t& r1,
                                       uint32_t& r2, uint32_t& r3, uint32_t a) {
    asm volatile("ldmatrix.sync.aligned.m8n8.x4.shared.b16 {%0,%1,%2,%3}, [%4+%5];"
                 : "=r"(r0), "=r"(r1), "=r"(r2), "=r"(r3) : "r"(a), "n"(IMM));
}
#define LDM4(f, base) do {                                        \
    ldmx4i<0>   ((f)[0][0], (f)[0][1], (f)[0][2], (f)[0][3], base); \
    ldmx4i<2048>((f)[1][0], (f)[1][1], (f)[1][2], (f)[1][3], base); \
    ldmx4i<4096>((f)[2][0], (f)[2][1], (f)[2][2], (f)[2][3], base); \
    ldmx4i<6144>((f)[3][0], (f)[3][1], (f)[3][2], (f)[3][3], base); \
} while (0)
#define LDM2(f, base) do {                                        \
    ldmx4i<0>   ((f)[0][0], (f)[0][1], (f)[0][2], (f)[0][3], base); \
    ldmx4i<2048>((f)[1][0], (f)[1][1], (f)[1][2], (f)[1][3], base); \
} while (0)

__device__ __forceinline__ void mma16816(float* c, const uint32_t* a,
                                         uint32_t b0, uint32_t b1) {
    asm("mma.sync.aligned.m16n8k16.row.col.f32.f16.f16.f32 "
        "{%0,%1,%2,%3}, {%4,%5,%6,%7}, {%8,%9}, {%0,%1,%2,%3};"
        : "+f"(c[0]), "+f"(c[1]), "+f"(c[2]), "+f"(c[3])
        : "r"(a[0]), "r"(a[1]), "r"(a[2]), "r"(a[3]), "r"(b0), "r"(b1));
}
__device__ __forceinline__ void imma16832(int* c, const uint32_t* a,
                                          uint32_t b0, uint32_t b1) {
    asm("mma.sync.aligned.m16n8k32.row.col.s32.s8.s8.s32 "
        "{%0,%1,%2,%3}, {%4,%5,%6,%7}, {%8,%9}, {%0,%1,%2,%3};"
        : "+r"(c[0]), "+r"(c[1]), "+r"(c[2]), "+r"(c[3])
        : "r"(a[0]), "r"(a[1]), "r"(a[2]), "r"(a[3]), "r"(b0), "r"(b1));
}

/* ================================================================== */
/* int8 3-term GEMM (NT): out = sa[m]*sb[n]*(HH + (HL+LH)/256) + bias  */
/* CTA 128x128, 8 warps 64x32 (2x4), k128 chunks, double-buffered.     */
/* ================================================================== */
#define PL8 16384                      /* plane bytes: 128 rows x 128B */
#define I8BUF (4*PL8)                  /* Ah|Al|Bh|Bl = 64KB */
#define I8SMEM (2*I8BUF)               /* 131072 */

template<bool ROPE>
__global__ void __launch_bounds__(256, 1) gemm_i8(
    const char* __restrict__ Ah, const char* __restrict__ Al,
    const char* __restrict__ Bh, const char* __restrict__ Bl,
    const float* __restrict__ sa, const float* __restrict__ sbn,
    const float* __restrict__ bias, float* __restrict__ C,
    const float* __restrict__ remb, int M, int N, int K) {
    extern __shared__ __align__(128) char smem[];
    uint32_t sb = smem_u32(smem);
    int tid = threadIdx.x, wid = tid >> 5, lane = tid & 31;
    int wm = wid >> 2, wn = wid & 3;
    int bm = blockIdx.y * 128, bn = blockIdx.x * 128;

    int rowL = lane & 15, kg = lane >> 4;
    int swz = rowL & 7;
    uint32_t koff[4];
    #pragma unroll
    for (int ks = 0; ks < 4; ks++)
        koff[ks] = (uint32_t)(((ks * 2 + kg) ^ swz) * 16);
    uint32_t aBase0 = sb           + (uint32_t)(wm * 64 + rowL) * 128u;
    uint32_t bBase0 = sb + 2*PL8   + (uint32_t)(wn * 32 + rowL) * 128u;

    int acch[4][4][4], accc[4][4][4];
    #pragma unroll
    for (int i = 0; i < 4; i++)
        #pragma unroll
        for (int j = 0; j < 4; j++)
            #pragma unroll
            for (int e = 0; e < 4; e++) { acch[i][j][e] = 0; accc[i][j][e] = 0; }

    int nch = K >> 7;

    auto load_chunk = [&](uint32_t dst, int ko) {
        #pragma unroll
        for (int j = 0; j < 4; j++) {
            int id = tid + j * 256;
            int row = id >> 3, g = id & 7;
            uint32_t off = (uint32_t)row * 128u + (uint32_t)((g ^ (row & 7)) * 16);
            size_t ao = (size_t)(bm + row) * K + ko + g * 16;
            size_t bo = (size_t)(bn + row) * K + ko + g * 16;
            cp16(dst + off,          Ah + ao);
            cp16(dst + PL8 + off,    Al + ao);
            cp16(dst + 2*PL8 + off,  Bh + bo);
            cp16(dst + 3*PL8 + off,  Bl + bo);
        }
    };

    load_chunk(sb, 0);
    cp_commit();

    for (int c = 0; c < nch; c++) {
        if (c + 1 < nch) {
            load_chunk(sb + (uint32_t)(((c + 1) & 1) * I8BUF), (c + 1) * 128);
            cp_commit();
            cp_wait<1>();
        } else {
            cp_wait<0>();
        }
        __syncthreads();

        uint32_t bofs = (uint32_t)(((c & 1) ? I8BUF : 0));
        uint32_t aB = aBase0 + bofs, bB = bBase0 + bofs;

        #pragma unroll
        for (int ks = 0; ks < 4; ks++) {
            uint32_t ko = koff[ks];
            /* term HH */
            uint32_t afh[4][4], bfh[2][4];
            LDM4(afh, aB + ko);
            LDM2(bfh, bB + 2*PL8 - 2*PL8 + 2*PL8*0 + ko + 0);   /* placeholder removed below */
            /* (bfh actually loads from Bh plane base) */
            (void)bfh;
            LDM2(bfh, bB + ko);
            #pragma unroll
            for (int mf = 0; mf < 4; mf++)
                #pragma unroll
                for (int nf = 0; nf < 4; nf++)
                    imma16832(acch[mf][nf], afh[mf],
                              bfh[nf >> 1][nf & 1], bfh[nf >> 1][(nf & 1) + 2]);
            /* term HL */
            {
                uint32_t bfl[2][4];
                LDM2(bfl, bB + PL8 + ko);
                #pragma unroll
                for (int mf = 0; mf < 4; mf++)
                    #pragma unroll
                    for (int nf = 0; nf < 4; nf++)
                        imma16832(accc[mf][nf], afh[mf],
                                  bfl[nf >> 1][nf & 1], bfl[nf >> 1][(nf & 1) + 2]);
            }
            /* term LH */
            {
                uint32_t afl[4][4];
                LDM4(afl, aB + PL8 + ko);
                #pragma unroll
                for (int mf = 0; mf < 4; mf++)
                    #pragma unroll
                    for (int nf = 0; nf < 4; nf++)
                        imma16832(accc[mf][nf], afl[mf],
                                  bfh[nf >> 1][nf & 1], bfh[nf >> 1][(nf & 1) + 2]);
            }
        }
        __syncthreads();
    }

    /* epilogue: dequant + bias (+rope) */
    int r0 = lane >> 2, cb = (lane & 3) * 2;
    #pragma unroll
    for (int mf = 0; mf < 4; mf++) {
        #pragma unroll
        for (int nf = 0; nf < 4; nf++) {
            int n0 = bn + wn * 32 + nf * 8 + cb;
            float sb0 = sbn[n0], sb1 = sbn[n0 + 1];
            float bz0 = bias[n0], bz1 = bias[n0 + 1];
            #pragma unroll
            for (int half = 0; half < 2; half++) {
                int m0 = bm + wm * 64 + mf * 16 + r0 + half * 8;
                float sam = sa[m0];
                float v0 = sam * sb0 * ((float)acch[mf][nf][half*2]
                         + (float)accc[mf][nf][half*2]     * 0.00390625f) + bz0;
                float v1 = sam * sb1 * ((float)acch[mf][nf][half*2+1]
                         + (float)accc[mf][nf][half*2+1]   * 0.00390625f) + bz1;
                if (ROPE) {
                    if (n0 < 2*DIM) {
                        int pos = m0 & (NTOK - 1);
                        int d   = n0 & (HD - 1);
                        const float* e = remb + pos * (2*HD);
                        float2 sn = *(const float2*)(e + d);
                        float2 cs = *(const float2*)(e + HD + d);
                        float t0 = v0 * cs.x - v1 * sn.x;
                        float t1 = v1 * cs.y + v0 * sn.y;
                        v0 = t0; v1 = t1;
                    }
                }
                *(float2*)(C + (size_t)m0 * N + n0) = make_float2(v0, v1);
            }
        }
    }
}

/* ================================================================== */
/* fp16 split-K partial GEMM (kept for O-proj / W2)                    */
/* ================================================================== */
#define PA 16384
#define PB 32768
#define BUFSZ (2*PA + 2*PB)
#define GEMM_SMEM (2*BUFSZ)

__global__ void __launch_bounds__(256, 1) gemm_fp16_part(
    const __half* __restrict__ Ahi, const __half* __restrict__ Alo,
    const __half* __restrict__ Bhi, const __half* __restrict__ Blo,
    float* __restrict__ C, int M, int N, int K) {
    extern __shared__ __align__(128) char smem[];
    uint32_t sb = smem_u32(smem);
    int tid = threadIdx.x, wid = tid >> 5, lane = tid & 31;
    int wm = wid >> 2, wn = wid & 3;
    int bm = blockIdx.y * 128, bn = blockIdx.x * 256;

    int l15 = lane & 15, kg = lane >> 4;
    uint32_t arow = (uint32_t)(wm * 64 + l15);
    uint32_t brow = (uint32_t)(wn * 64 + l15);
    int aswz = (int)(arow & 7), bswz = (int)(brow & 7);

    uint32_t aoff[4], boff[4];
    #pragma unroll
    for (int ks = 0; ks < 4; ks++) {
        int g = ks * 2 + kg;
        aoff[ks] = (uint32_t)((g ^ aswz) * 16);
        boff[ks] = (uint32_t)((g ^ bswz) * 16);
    }
    uint32_t aHi0 = sb             + arow * 128u;
    uint32_t aLo0 = sb + PA        + arow * 128u;
    uint32_t bHi0 = sb + 2*PA      + brow * 128u;
    uint32_t bLo0 = sb + 2*PA + PB + brow * 128u;

    float acc[4][8][4];
    #pragma unroll
    for (int i = 0; i < 4; i++)
        #pragma unroll
        for (int j = 0; j < 8; j++)
            #pragma unroll
            for (int e = 0; e < 4; e++) acc[i][j][e] = 0.f;

    int nch = K >> 6;
    int z = blockIdx.z;
    int c0 = (z * nch) / 3;
    int c1 = ((z + 1) * nch) / 3;

    auto load_chunk = [&](uint32_t dst, int ko) {
        #pragma unroll
        for (int j = 0; j < 4; j++) {
            int id = tid + j * 256;
            int row = id >> 3, g = id & 7;
            uint32_t off = (uint32_t)row * 128u + (uint32_t)((g ^ (row & 7)) * 16);
            size_t so = (size_t)(bm + row) * K + ko + g * 8;
            cp16(dst + off,      Ahi + so);
            cp16(dst + PA + off, Alo + so);
        }
        #pragma unroll
        for (int j = 0; j < 8; j++) {
            int id = tid + j * 256;
            int row = id >> 3, g = id & 7;
            uint32_t off = (uint32_t)row * 128u + (uint32_t)((g ^ (row & 7)) * 16);
            size_t so = (size_t)(bn + row) * K + ko + g * 8;
            cp16(dst + 2*PA + off,      Bhi + so);
            cp16(dst + 2*PA + PB + off, Blo + so);
        }
    };

    load_chunk(sb, c0 * 64);
    cp_commit();

    for (int c = c0; c < c1; c++) {
        if (c + 1 < c1) {
            load_chunk(sb + (uint32_t)(((c - c0 + 1) & 1) * BUFSZ), (c + 1) * 64);
            cp_commit();
            cp_wait<1>();
        } else {
            cp_wait<0>();
        }
        __syncthreads();

        uint32_t bofs = (uint32_t)(((c - c0) & 1) ? BUFSZ : 0);
        uint32_t a_hi = aHi0 + bofs, a_lo = aLo0 + bofs;
        uint32_t b_hi = bHi0 + bofs, b_lo = bLo0 + bofs;

        #pragma unroll
        for (int ks = 0; ks < 4; ks++) {
            uint32_t afh[4][4], bfh[4][4];
            LDM4(afh, a_hi + aoff[ks]);
            LDM4(bfh, b_hi + boff[ks]);
            #pragma unroll
            for (int mf = 0; mf < 4; mf++)
                #pragma unroll
                for (int nf = 0; nf < 8; nf++)
                    mma16816(acc[mf][nf], afh[mf],
                             bfh[nf >> 1][nf & 1], bfh[nf >> 1][(nf & 1) + 2]);
            {
                uint32_t bfl[4][4];
                LDM4(bfl, b_lo + boff[ks]);
                #pragma unroll
                for (int mf = 0; mf < 4; mf++)
                    #pragma unroll
                    for (int nf = 0; nf < 8; nf++)
                        mma16816(acc[mf][nf], afh[mf],
                                 bfl[nf >> 1][nf & 1], bfl[nf >> 1][(nf & 1) + 2]);
            }
            {
                uint32_t afl[4][4];
                LDM4(afl, a_lo + aoff[ks]);
                #pragma unroll
                for (int mf = 0; mf < 4; mf++)
                    #pragma unroll
                    for (int nf = 0; nf < 8; nf++)
                        mma16816(acc[mf][nf], afl[mf],
                                 bfh[nf >> 1][nf & 1], bfh[nf >> 1][(nf & 1) + 2]);
            }
        }
        __syncthreads();
    }

    int r0 = lane >> 2, cb = (lane & 3) * 2;
    float* Cp = C + (size_t)blockIdx.z * M * N;
    #pragma unroll
    for (int mf = 0; mf < 4; mf++)
        #pragma unroll
        for (int nf = 0; nf < 8; nf++) {
            int n0 = bn + wn * 64 + nf * 8 + cb;
            #pragma unroll
            for (int half = 0; half < 2; half++) {
                int m0 = bm + wm * 64 + mf * 16 + r0 + half * 8;
                *(float2*)(Cp + (size_t)m0 * N + n0) =
                    make_float2(acc[mf][nf][half * 2], acc[mf][nf][half * 2 + 1]);
            }
        }
}

/* ------------------------------------------------------------------ */
/* reduce3: h += bias + p0 + p1 + p2                                   */
/* ------------------------------------------------------------------ */
__global__ void reduce3(float* __restrict__ h, const float* __restrict__ part,
                        const float* __restrict__ bias) {
    int i = blockIdx.x * blockDim.x + threadIdx.x;
    if (i >= TOKENS*DIM/4) return;
    float4 a  = ((const float4*)h)[i];
    float4 p0 = ((const float4*)part)[i];
    float4 p1 = ((const float4*)(part + TOKENS*DIM))[i];
    float4 p2 = ((const float4*)(part + 2*TOKENS*DIM))[i];
    float4 bz = *(const float4*)(bias + (i*4) % DIM);
    a.x += bz.x + ((p0.x + p1.x) + p2.x);
    a.y += bz.y + ((p0.y + p1.y) + p2.y);
    a.z += bz.z + ((p0.z + p1.z) + p2.z);
    a.w += bz.w + ((p0.w + p1.w) + p2.w);
    ((float4*)h)[i] = a;
}

/* ------------------------------------------------------------------ */
/* fp16 split cvt for WO + W2 only                                     */
/* ------------------------------------------------------------------ */
__device__ __forceinline__ void split2(float a, float b, __half2& h, __half2& l) {
    __half ha = __float2half_rn(a), hb = __float2half_rn(b);
    __half la = __float2half_rn(a - __half2float(ha));
    __half lb = __float2half_rn(b - __half2float(hb));
    h = __halves2half2(ha, hb);
    l = __halves2half2(la, lb);
}
__global__ void cvt_fp16(const float* __restrict__ wo, const float* __restrict__ w2,
                         __half* __restrict__ woh, __half* __restrict__ wol,
                         __half* __restrict__ w2h, __half* __restrict__ w2l) {
    int i4 = blockIdx.x * blockDim.x + threadIdx.x;
    const int nD4 = DEPTH*DIM*DIM/4, nH4 = DEPTH*DIM*HIDDEN/4;
    if (i4 >= nD4 + nH4) return;
    const float* s; __half *hi, *lo; int i;
    if (i4 < nD4) { s = wo; hi = woh; lo = wol; i = i4 * 4; }
    else          { s = w2; hi = w2h; lo = w2l; i = (i4 - nD4) * 4; }
    float4 v = *(const float4*)(s + i);
    __half2 h0, l0, h1, l1;
    split2(v.x, v.y, h0, l0);
    split2(v.z, v.w, h1, l1);
    ((__half2*)(hi + i))[0] = h0; ((__half2*)(hi + i))[1] = h1;
    ((__half2*)(lo + i))[0] = l0; ((__half2*)(lo + i))[1] = l1;
}

/* ------------------------------------------------------------------ */
/* int8 weight quant: one warp per output row (K=768)                  */
/* ------------------------------------------------------------------ */
__global__ void cvt_w8(const float* __restrict__ wq, const float* __restrict__ wk,
                       const float* __restrict__ wv, const float* __restrict__ w1g,
                       const float* __restrict__ w1x,
                       char* __restrict__ qh, char* __restrict__ ql,
                       float* __restrict__ sq,
                       char* __restrict__ uh, char* __restrict__ ul,
                       float* __restrict__ su) {
    const int NQ = DEPTH*QS, NU = DEPTH*GUS;
    int w = (blockIdx.x * blockDim.x + threadIdx.x) >> 5;
    int lane = threadIdx.x & 31;
    if (w >= NQ + NU) return;
    const int nD = DIM*DIM, nH = HIDDEN*DIM;
    const float* src; char *dh, *dl; float* ds; size_t drow; int ridx;
    if (w < NQ) {
        int l = w / QS, c = w % QS;
        src = (c < DIM)    ? wq + (size_t)l*nD + (size_t)c*DIM
            : (c < 2*DIM)  ? wk + (size_t)l*nD + (size_t)(c - DIM)*DIM
                           : wv + (size_t)l*nD + (size_t)(c - 2*DIM)*DIM;
        dh = qh; dl = ql; ds = sq; drow = (size_t)w * DIM; ridx = w;
    } else {
        int r2 = w - NQ;
        int l = r2 / GUS, c = r2 % GUS;
        src = (c < HIDDEN) ? w1g + (size_t)l*nH + (size_t)c*DIM
                           : w1x + (size_t)l*nH + (size_t)(c - HIDDEN)*DIM;
        dh = uh; dl = ul; ds = su; drow = (size_t)r2 * DIM; ridx = r2;
    }
    float4 vv[6];
    float mx = 0.f;
    #pragma unroll
    for (int i = 0; i < 6; i++) {
        vv[i] = ((const float4*)src)[lane + i * 32];
        mx = fmaxf(mx, fmaxf(fmaxf(fabsf(vv[i].x), fabsf(vv[i].y)),
                             fmaxf(fabsf(vv[i].z), fabsf(vv[i].w))));
    }
    #pragma unroll
    for (int o = 16; o > 0; o >>= 1)
        mx = fmaxf(mx, __shfl_xor_sync(0xffffffffu, mx, o));
    float sav = fmaxf(mx, 1e-30f) * (1.f / 127.f);
    float rs = 1.f / sav;
    #pragma unroll
    for (int i = 0; i < 6; i++) {
        float q[4] = { vv[i].x*rs, vv[i].y*rs, vv[i].z*rs, vv[i].w*rs };
        char hc[4], lc[4];
        #pragma unroll
        for (int e = 0; e < 4; e++) {
            int hi = __float2int_rn(q[e]);
            int lo = __float2int_rn((q[e] - (float)hi) * 256.f);
            lo = max(-127, min(127, lo));
            hc[e] = (char)hi; lc[e] = (char)lo;
        }
        *(char4*)(dh + drow + (lane + i*32)*4) = make_char4(hc[0],hc[1],hc[2],hc[3]);
        *(char4*)(dl + drow + (lane + i*32)*4) = make_char4(lc[0],lc[1],lc[2],lc[3]);
    }
    if (lane == 0) ds[ridx] = sav;
}

/* ------------------------------------------------------------------ */
/* add_pos + bias packing fused                                        */
/* ------------------------------------------------------------------ */
__global__ void add_pos_prep(const float* __restrict__ x,
                             const float* __restrict__ pos,
                             float* __restrict__ h,
                             const float* __restrict__ bq,
                             const float* __restrict__ bv,
                             float* __restrict__ bqkv,
                             const float* __restrict__ bg,
                             const float* __restrict__ bx,
                             float* __restrict__ b1) {
    int idx = blockIdx.x * blockDim.x + threadIdx.x;
    if (idx < TOKENS*DIM) h[idx] = x[idx] + pos[idx % (NTOK*DIM)];
    if (idx < DEPTH*QS) {
        int l = idx / QS, c = idx % QS;
        bqkv[idx] = c < DIM ? bq[l*DIM + c]
                  : (c < 2*DIM ? 0.f : bv[l*DIM + c - 2*DIM]);
    }
    if (idx < DEPTH*GUS) {
        int l = idx / GUS, c = idx % GUS;
        b1[idx] = c < HIDDEN ? bg[l*HIDDEN + c] : bx[l*HIDDEN + c - HIDDEN];
    }
}

/* ------------------------------------------------------------------ */
/* Block reductions (256 threads)                                      */
/* ------------------------------------------------------------------ */
__device__ __forceinline__ float2 block_reduce_2(float s, float s2) {
    __shared__ float red[16];
    #pragma unroll
    for (int o = 16; o > 0; o >>= 1) {
        s  += __shfl_down_sync(0xffffffffu, s,  o);
        s2 += __shfl_down_sync(0xffffffffu, s2, o);
    }
    int w = threadIdx.x >> 5, l = threadIdx.x & 31;
    if (l == 0) { red[w] = s; red[8 + w] = s2; }
    __syncthreads();
    if (threadIdx.x < 32) {
        s  = (l < 8) ? red[l]     : 0.f;
        s2 = (l < 8) ? red[8 + l] : 0.f;
        #pragma unroll
        for (int o = 4; o > 0; o >>= 1) {
            s  += __shfl_down_sync(0xffffffffu, s,  o);
            s2 += __shfl_down_sync(0xffffffffu, s2, o);
        }
        if (l == 0) { red[0] = s; red[1] = s2; }
    }
    __syncthreads();
    return make_float2(red[0], red[1]);
}
__device__ __forceinline__ float block_reduce_max(float m) {
    __shared__ float redm[8];
    #pragma unroll
    for (int o = 16; o > 0; o >>= 1)
        m = fmaxf(m, __shfl_down_sync(0xffffffffu, m, o));
    int w = threadIdx.x >> 5, l = threadIdx.x & 31;
    if (l == 0) redm[w] = m;
    __syncthreads();
    if (threadIdx.x < 32) {
        m = (l < 8) ? redm[l] : 0.f;
        #pragma unroll
        for (int o = 4; o > 0; o >>= 1)
            m = fmaxf(m, __shfl_down_sync(0xffffffffu, m, o));
        if (l == 0) redm[0] = m;
    }
    __syncthreads();
    return redm[0];
}

__device__ __forceinline__ uint32_t pack_h2(float a, float b) {
    __half2 h = __floats2half2_rn(a, b);
    return *(uint32_t*)&h;
}

/* ------------------------------------------------------------------ */
/* LayerNorm over DIM with int8 hi/lo quantized output                 */
/* ------------------------------------------------------------------ */
__global__ void __launch_bounds__(256) ln_q_kernel(
    const float* __restrict__ x, const float* __restrict__ w,
    const float* __restrict__ b, char* __restrict__ qh,
    char* __restrict__ ql, float* __restrict__ sav) {
    int t = blockIdx.x;
    int c4 = threadIdx.x;
    float4 v = make_float4(0.f, 0.f, 0.f, 0.f);
    if (c4 < DIM/4) v = ((const float4*)(x + (size_t)t * DIM))[c4];
    float s  = v.x + v.y + v.z + v.w;
    float s2 = v.x*v.x + v.y*v.y + v.z*v.z + v.w*v.w;
    float2 r = block_reduce_2(s, s2);
    float mean = r.x / DIM;
    float var  = r.y / DIM - mean * mean;
    float inv  = rsqrtf(var + EPSF);
    float y[4] = {0.f, 0.f, 0.f, 0.f};
    float mx = 0.f;
    if (c4 < DIM/4) {
        float4 wv = ((const float4*)w)[c4];
        float4 bv = ((const float4*)b)[c4];
        y[0] = (v.x - mean) * inv * wv.x + bv.x;
        y[1] = (v.y - mean) * inv * wv.y + bv.y;
        y[2] = (v.z - mean) * inv * wv.z + bv.z;
        y[3] = (v.w - mean) * inv * wv.w + bv.w;
        mx = fmaxf(fmaxf(fabsf(y[0]), fabsf(y[1])),
                   fmaxf(fabsf(y[2]), fabsf(y[3])));
    }
    float rmax = block_reduce_max(mx);
    float sv = fmaxf(rmax, 1e-30f) * (1.f / 127.f);
    float rs = 1.f / sv;
    if (c4 < DIM/4) {
        char hc[4], lc[4];
        #pragma unroll
        for (int e = 0; e < 4; e++) {
            float q = y[e] * rs;
            int hi = __float2int_rn(q);
            int lo = __float2int_rn((q - (float)hi) * 256.f);
            lo = max(-127, min(127, lo));
            hc[e] = (char)hi; lc[e] = (char)lo;
        }
        *(char4*)(qh + (size_t)t * DIM + c4*4) = make_char4(hc[0],hc[1],hc[2],hc[3]);
        *(char4*)(ql + (size_t)t * DIM + c4*4) = make_char4(lc[0],lc[1],lc[2],lc[3]);
    }
    if (threadIdx.x == 0) sav[t] = sv;
}

/* ------------------------------------------------------------------ */
/* silu(g)*u then LN over HIDDEN -> fp16 hi/lo (feeds W2 fp16 path)    */
/* ------------------------------------------------------------------ */
__global__ void __launch_bounds__(256) mlp_act_ln_kernel(
    const float* __restrict__ gu,
    const float* __restrict__ w, const float* __restrict__ b,
    __half* __restrict__ ohi, __half* __restrict__ olo) {
    int t = blockIdx.x;
    const float* gr = gu + (size_t)t * GUS;
    const float* ur = gr + HIDDEN;
    float a[8];
    float s = 0.f, s2 = 0.f;
    #pragma unroll
    for (int j = 0; j < 2; j++) {
        int c4 = threadIdx.x + j * 256;
        float4 gv = ((const float4*)gr)[c4];
        float4 uv = ((const float4*)ur)[c4];
        float* aj = a + j * 4;
        aj[0] = gv.x / (1.f + __expf(-gv.x)) * uv.x;
        aj[1] = gv.y / (1.f + __expf(-gv.y)) * uv.y;
        aj[2] = gv.z / (1.f + __expf(-gv.z)) * uv.z;
        aj[3] = gv.w / (1.f + __expf(-gv.w)) * uv.w;
        s  += aj[0] + aj[1] + aj[2] + aj[3];
        s2 += aj[0]*aj[0] + aj[1]*aj[1] + aj[2]*aj[2] + aj[3]*aj[3];
    }
    float2 r = block_reduce_2(s, s2);
    float mean = r.x / HIDDEN;
    float var  = r.y / HIDDEN - mean * mean;
    float inv  = rsqrtf(var + EPSF);
    #pragma unroll
    for (int j = 0; j < 2; j++) {
        int c4 = threadIdx.x + j * 256;
        float4 wv = ((const float4*)w)[c4];
        float4 bv = ((const float4*)b)[c4];
        float* aj = a + j * 4;
        float y0 = (aj[0] - mean) * inv * wv.x + bv.x;
        float y1 = (aj[1] - mean) * inv * wv.y + bv.y;
        float y2 = (aj[2] - mean) * inv * wv.z + bv.z;
        float y3 = (aj[3] - mean) * inv * wv.w + bv.w;
        __half h0 = __float2half_rn(y0), h1 = __float2half_rn(y1);
        __half h2 = __float2half_rn(y2), h3 = __float2half_rn(y3);
        uint2 hi = make_uint2(pack_h2(y0, y1), pack_h2(y2, y3));
        uint2 lo = make_uint2(pack_h2(y0 - __half2float(h0), y1 - __half2float(h1)),
                              pack_h2(y2 - __half2float(h2), y3 - __half2float(h3)));
        ((uint2*)ohi)[(size_t)t * (HIDDEN/4) + c4] = hi;
        ((uint2*)olo)[(size_t)t * (HIDDEN/4) + c4] = lo;
    }
}

/* ------------------------------------------------------------------ */
/* Attention (unchanged; emits fp16 hi/lo for O-proj fp16 path)        */
/* ------------------------------------------------------------------ */
#define KVT 128
__global__ void __launch_bounds__(256) attn_kernel(
    const float* __restrict__ qkv, __half* __restrict__ ohi,
    __half* __restrict__ olo) {
    extern __shared__ float sm[];
    float* Ks = sm;
    float* Vs = sm + KVT * HD;
    int blk = blockIdx.x;
    int half_blk = blk & 1;
    int bh = blk >> 1;
    int b  = bh / HEADS, h = bh % HEADS;
    size_t base_q = (size_t)(b * NTOK) * QS + h * HD;
    int tid = threadIdx.x, lane = tid & 31, wid = tid >> 5;
    int row_local = wid * 16 + (lane & 15);
    int part = lane >> 4;
    int i = half_blk * 128 + row_local;

    const float scale = 0.125f;
    float qreg[32];
    {
        const float* qp = qkv + base_q + (size_t)i * QS + part * 32;
        #pragma unroll
        for (int d = 0; d < 32; d++) qreg[d] = qp[d] * scale;
    }

    float mrun = -1e30f, lrun = 0.f;
    float accv[32];
    #pragma unroll
    for (int d = 0; d < 32; d++) accv[d] = 0.f;

    for (int tkv = 0; tkv < NTOK / KVT; tkv++) {
        for (int idx = tid; idx < KVT * HD; idx += 256) {
            int row = idx >> 6, col = idx & 63;
            size_t src = base_q + (size_t)(tkv * KVT + row) * QS + col;
            Ks[idx] = qkv[src + DIM];
            Vs[idx] = qkv[src + 2*DIM];
        }
        __syncthreads();

        for (int j = 0; j < KVT; j++) {
            const float* kr = Ks + j * HD + part * 32;
            float s = 0.f;
            #pragma unroll
            for (int d = 0; d < 32; d++) s += qreg[d] * kr[d];
            s += __shfl_xor_sync(0xffffffffu, s, 16);
            float mnew = fmaxf(mrun, s);
            float cc = __expf(mrun - mnew);
            float p  = __expf(s - mnew);
            lrun = lrun * cc + p;
            const float* vr = Vs + j * HD + part * 32;
            #pragma unroll
            for (int d = 0; d < 32; d++) accv[d] = accv[d] * cc + p * vr[d];
            mrun = mnew;
        }
        __syncthreads();
    }

    float inv = 1.f / lrun;
    size_t ob = (size_t)(b * NTOK + i) * DIM + h * HD + part * 32;
    #pragma unroll
    for (int d = 0; d < 32; d++) {
        float v0 = accv[d] * inv;
        __half hh = __float2half_rn(v0);
        ohi[ob + d] = hh;
        olo[ob + d] = __float2half_rn(v0 - __half2float(hh));
    }
}

/* ------------------------------------------------------------------ */
/* Launch                                                              */
/* ------------------------------------------------------------------ */
extern "C" void kernel_launch(void* const* d_in, const int* in_sizes, int n_in,
                              void* d_out, int out_size) {
    const float* x      = (const float*)d_in[0];
    const float* pos    = (const float*)d_in[1];
    const float* rope   = (const float*)d_in[2];
    const float* ln1_w  = (const float*)d_in[3];
    const float* ln1_b  = (const float*)d_in[4];
    const float* wq     = (const float*)d_in[5];
    const float* bq     = (const float*)d_in[6];
    const float* wk     = (const float*)d_in[7];
    const float* wv     = (const float*)d_in[8];
    const float* bv     = (const float*)d_in[9];
    const float* wo     = (const float*)d_in[10];
    const float* bo     = (const float*)d_in[11];
    const float* ln2_w  = (const float*)d_in[12];
    const float* ln2_b  = (const float*)d_in[13];
    const float* w1g    = (const float*)d_in[14];
    const float* b1g    = (const float*)d_in[15];
    const float* w1x    = (const float*)d_in[16];
    const float* b1x    = (const float*)d_in[17];
    const float* lnm_w  = (const float*)d_in[18];
    const float* lnm_b  = (const float*)d_in[19];
    const float* w2     = (const float*)d_in[20];
    const float* b2     = (const float*)d_in[21];
    float* h = (float*)d_out;

    float *qkv, *gu, *bqkv, *b1, *part, *say, *sbqkv, *sb1;
    __half *ohh, *ohl, *mhh, *mhl, *woh, *wol, *w2h, *w2l;
    char *yqh, *yql, *wqkvh8, *wqkvl8, *w1h8, *w1l8;
    cudaGetSymbolAddress((void**)&qkv,    g_qkv);
    cudaGetSymbolAddress((void**)&gu,     g_gu);
    cudaGetSymbolAddress((void**)&part,   g_part);
    cudaGetSymbolAddress((void**)&bqkv,   g_bqkv);
    cudaGetSymbolAddress((void**)&b1,     g_b1);
    cudaGetSymbolAddress((void**)&say,    g_say);
    cudaGetSymbolAddress((void**)&sbqkv,  g_sbqkv);
    cudaGetSymbolAddress((void**)&sb1,    g_sb1);
    cudaGetSymbolAddress((void**)&ohh,    g_oh_hi);
    cudaGetSymbolAddress((void**)&ohl,    g_oh_lo);
    cudaGetSymbolAddress((void**)&mhh,    g_mh_hi);
    cudaGetSymbolAddress((void**)&mhl,    g_mh_lo);
    cudaGetSymbolAddress((void**)&woh,    g_wo_hi);
    cudaGetSymbolAddress((void**)&wol,    g_wo_lo);
    cudaGetSymbolAddress((void**)&w2h,    g_w2_hi);
    cudaGetSymbolAddress((void**)&w2l,    g_w2_lo);
    cudaGetSymbolAddress((void**)&yqh,    g_yq_h);
    cudaGetSymbolAddress((void**)&yql,    g_yq_l);
    cudaGetSymbolAddress((void**)&wqkvh8, g_wqkv_h);
    cudaGetSymbolAddress((void**)&wqkvl8, g_wqkv_l);
    cudaGetSymbolAddress((void**)&w1h8,   g_w1_h);
    cudaGetSymbolAddress((void**)&w1l8,   g_w1_l);

    cudaFuncSetAttribute((const void*)gemm_i8<true>,
                         cudaFuncAttributeMaxDynamicSharedMemorySize, I8SMEM);
    cudaFuncSetAttribute((const void*)gemm_i8<false>,
                         cudaFuncAttributeMaxDynamicSharedMemorySize, I8SMEM);
    cudaFuncSetAttribute((const void*)gemm_fp16_part,
                         cudaFuncAttributeMaxDynamicSharedMemorySize, GEMM_SMEM);
    cudaFuncSetAttribute((const void*)attn_kernel,
                         cudaFuncAttributeMaxDynamicSharedMemorySize,
                         2 * KVT * HD * (int)sizeof(float));

    /* ---- weight conversion ---- */
    {
        const int nTot4 = (DEPTH*DIM*DIM + DEPTH*DIM*HIDDEN) / 4;
        cvt_fp16<<<(nTot4 + 255)/256, 256>>>(wo, w2, woh, wol, w2h, w2l);
        const int nwarps = DEPTH*QS + DEPTH*GUS;
        cvt_w8<<<(nwarps*32 + 255)/256, 256>>>(wq, wk, wv, w1g, w1x,
                                               wqkvh8, wqkvl8, sbqkv,
                                               w1h8, w1l8, sb1);
    }
    add_pos_prep<<<(TOKENS*DIM + 255)/256, 256>>>(x, pos, h, bq, bv, bqkv,
                                                  b1g, b1x, b1);

    dim3 gQKV(QS/128,  TOKENS/128);      /* (18, 32)   */
    dim3 gMLP(GUS/128, TOKENS/128);      /* (32, 32)   */
    dim3 gSK (DIM/256, TOKENS/128, 3);   /* (3, 32, 3) */
    const int RED = (TOKENS*DIM/4 + 255)/256;

    for (int l = 0; l < DEPTH; l++) {
        size_t oqkv = (size_t)l * QS * DIM;
        size_t owo  = (size_t)l * DIM * DIM;
        size_t ow1  = (size_t)l * GUS * DIM;
        size_t ow2  = (size_t)l * DIM * HIDDEN;

        /* ---- attention ---- */
        ln_q_kernel<<<TOKENS, 256>>>(h, ln1_w + l*DIM, ln1_b + l*DIM, yqh, yql, say);
        gemm_i8<true><<<gQKV, 256, I8SMEM>>>(
            yqh, yql, wqkvh8 + oqkv, wqkvl8 + oqkv,
            say, sbqkv + l*QS, bqkv + l*QS, qkv, rope, TOKENS, QS, DIM);
        attn_kernel<<<BATCH*HEADS*2, 256, 2*KVT*HD*sizeof(float)>>>(qkv, ohh, ohl);
        gemm_fp16_part<<<gSK, 256, GEMM_SMEM>>>(
            ohh, ohl, woh + owo, wol + owo, part, TOKENS, DIM, DIM);
        reduce3<<<RED, 256>>>(h, part, bo + l*DIM);

        /* ---- SwiGLU MLP ---- */
        ln_q_kernel<<<TOKENS, 256>>>(h, ln2_w + l*DIM, ln2_b + l*DIM, yqh, yql, say);
        gemm_i8<false><<<gMLP, 256, I8SMEM>>>(
            yqh, yql, w1h8 + ow1, w1l8 + ow1,
            say, sb1 + l*GUS, b1 + l*GUS, gu, nullptr, TOKENS, GUS, DIM);
        mlp_act_ln_kernel<<<TOKENS, 256>>>(gu, lnm_w + l*HIDDEN, lnm_b + l*HIDDEN, mhh, mhl);
        gemm_fp16_part<<<gSK, 256, GEMM_SMEM>>>(
            mhh, mhl, w2h + ow2, w2l + ow2, part, TOKENS, DIM, HIDDEN);
        reduce3<<<RED, 256>>>(h, part, b2 + l*DIM);
    }
}

// round 13
// speedup vs baseline: 1.8086x; 1.8086x over previous
#include <cuda_runtime.h>
#include <cuda_fp16.h>
#include <math.h>
#include <stdint.h>

#define DEPTH   12
#define BATCH   16
#define NTOK    256
#define TOKENS  (BATCH*NTOK)     /* 4096 */
#define DIM     768
#define HEADS   12
#define HD      64
#define HIDDEN  2048
#define EPSF    1e-5f
#define QS      2304             /* packed qkv row stride */
#define GUS     4096             /* packed g|u row stride */

/* ------------------------------------------------------------------ */
/* Scratch buffers                                                     */
/* ------------------------------------------------------------------ */
__device__ float  g_qkv[TOKENS*QS];
__device__ float  g_gu[TOKENS*GUS];
__device__ float  g_part[3*TOKENS*DIM];
__device__ __half g_yh_hi[TOKENS*DIM];
__device__ __half g_yh_lo[TOKENS*DIM];
__device__ __half g_oh_hi[TOKENS*DIM];
__device__ __half g_oh_lo[TOKENS*DIM];
__device__ __half g_mh_hi[TOKENS*HIDDEN];
__device__ __half g_mh_lo[TOKENS*HIDDEN];

/* packed split weights */
__device__ __half g_wqkv_hi[DEPTH*QS*DIM];
__device__ __half g_wqkv_lo[DEPTH*QS*DIM];
__device__ __half g_wo_hi[DEPTH*DIM*DIM];
__device__ __half g_wo_lo[DEPTH*DIM*DIM];
__device__ __half g_w1_hi[DEPTH*GUS*DIM];
__device__ __half g_w1_lo[DEPTH*GUS*DIM];
__device__ __half g_w2_hi[DEPTH*DIM*HIDDEN];
__device__ __half g_w2_lo[DEPTH*DIM*HIDDEN];
__device__ float  g_bqkv[DEPTH*QS];
__device__ float  g_b1[DEPTH*GUS];

/* ------------------------------------------------------------------ */
/* PTX helpers                                                         */
/* ------------------------------------------------------------------ */
__device__ __forceinline__ uint32_t smem_u32(const void* p) {
    uint32_t a;
    asm("{ .reg .u64 t; cvta.to.shared.u64 t, %1; cvt.u32.u64 %0, t; }"
        : "=r"(a) : "l"(p));
    return a;
}
__device__ __forceinline__ void cp16(uint32_t dst, const void* src) {
    asm volatile("cp.async.cg.shared.global [%0], [%1], 16;"
                 :: "r"(dst), "l"(src) : "memory");
}
__device__ __forceinline__ void cp_commit() {
    asm volatile("cp.async.commit_group;" ::: "memory");
}
template<int NWAIT>
__device__ __forceinline__ void cp_wait() {
    asm volatile("cp.async.wait_group %0;" :: "n"(NWAIT) : "memory");
}
template<int IMM>
__device__ __forceinline__ void ldmx4i(uint32_t& r0, uint32_t& r1,
                                       uint32_t& r2, uint32_t& r3, uint32_t a) {
    asm volatile("ldmatrix.sync.aligned.m8n8.x4.shared.b16 {%0,%1,%2,%3}, [%4+%5];"
                 : "=r"(r0), "=r"(r1), "=r"(r2), "=r"(r3) : "r"(a), "n"(IMM));
}
#define LDM4(f, base) do {                                        \
    ldmx4i<0>   ((f)[0][0], (f)[0][1], (f)[0][2], (f)[0][3], base); \
    ldmx4i<2048>((f)[1][0], (f)[1][1], (f)[1][2], (f)[1][3], base); \
    ldmx4i<4096>((f)[2][0], (f)[2][1], (f)[2][2], (f)[2][3], base); \
    ldmx4i<6144>((f)[3][0], (f)[3][1], (f)[3][2], (f)[3][3], base); \
} while (0)

__device__ __forceinline__ void mma16816(float* c, const uint32_t* a,
                                         uint32_t b0, uint32_t b1) {
    asm("mma.sync.aligned.m16n8k16.row.col.f32.f16.f16.f32 "
        "{%0,%1,%2,%3}, {%4,%5,%6,%7}, {%8,%9}, {%0,%1,%2,%3};"
        : "+f"(c[0]), "+f"(c[1]), "+f"(c[2]), "+f"(c[3])
        : "r"(a[0]), "r"(a[1]), "r"(a[2]), "r"(a[3]), "r"(b0), "r"(b1));
}

/* ------------------------------------------------------------------ */
/* Split-fp16 HMMA GEMM (NT): C = Ahi*Bhi + Ahi*Blo + Alo*Bhi          */
/* CTA tile 128x256, 8 warps of 64x64 (2x4), BK=64, double-buffered.   */
/* ------------------------------------------------------------------ */
#define PA 16384
#define PB 32768
#define BUFSZ (2*PA + 2*PB)            /* 98304 */
#define GEMM_SMEM (2*BUFSZ)            /* 196608 */

template<bool ROPE, bool PARTIAL>
__global__ void __launch_bounds__(256, 1) gemm_mma(
    const __half* __restrict__ Ahi, const __half* __restrict__ Alo,
    const __half* __restrict__ Bhi, const __half* __restrict__ Blo,
    const float* __restrict__ bias, const float* __restrict__ res,
    float* __restrict__ C, const float* __restrict__ remb,
    int M, int N, int K) {
    extern __shared__ __align__(128) char smem[];
    uint32_t sb = smem_u32(smem);
    int tid = threadIdx.x, wid = tid >> 5, lane = tid & 31;
    int wm = wid >> 2, wn = wid & 3;
    int bm = blockIdx.y * 128, bn = blockIdx.x * 256;

    int l15 = lane & 15, kg = lane >> 4;
    uint32_t arow = (uint32_t)(wm * 64 + l15);
    uint32_t brow = (uint32_t)(wn * 64 + l15);
    int aswz = (int)(arow & 7), bswz = (int)(brow & 7);

    uint32_t aoff[4], boff[4];
    #pragma unroll
    for (int ks = 0; ks < 4; ks++) {
        int g = ks * 2 + kg;
        aoff[ks] = (uint32_t)((g ^ aswz) * 16);
        boff[ks] = (uint32_t)((g ^ bswz) * 16);
    }
    uint32_t aHi0 = sb             + arow * 128u;
    uint32_t aLo0 = sb + PA        + arow * 128u;
    uint32_t bHi0 = sb + 2*PA      + brow * 128u;
    uint32_t bLo0 = sb + 2*PA + PB + brow * 128u;

    float acc[4][8][4];
    #pragma unroll
    for (int i = 0; i < 4; i++)
        #pragma unroll
        for (int j = 0; j < 8; j++)
            #pragma unroll
            for (int e = 0; e < 4; e++) acc[i][j][e] = 0.f;

    int nch = K >> 6;
    int c0 = 0, c1 = nch;
    if (PARTIAL) {
        int z = blockIdx.z;
        c0 = (z * nch) / 3;
        c1 = ((z + 1) * nch) / 3;
    }

    auto load_chunk = [&](uint32_t dst, int ko) {
        #pragma unroll
        for (int j = 0; j < 4; j++) {
            int id = tid + j * 256;
            int row = id >> 3, g = id & 7;
            uint32_t off = (uint32_t)row * 128u + (uint32_t)((g ^ (row & 7)) * 16);
            size_t so = (size_t)(bm + row) * K + ko + g * 8;
            cp16(dst + off,      Ahi + so);
            cp16(dst + PA + off, Alo + so);
        }
        #pragma unroll
        for (int j = 0; j < 8; j++) {
            int id = tid + j * 256;
            int row = id >> 3, g = id & 7;
            uint32_t off = (uint32_t)row * 128u + (uint32_t)((g ^ (row & 7)) * 16);
            size_t so = (size_t)(bn + row) * K + ko + g * 8;
            cp16(dst + 2*PA + off,      Bhi + so);
            cp16(dst + 2*PA + PB + off, Blo + so);
        }
    };

    load_chunk(sb, c0 * 64);
    cp_commit();

    for (int c = c0; c < c1; c++) {
        if (c + 1 < c1) {
            load_chunk(sb + (uint32_t)(((c - c0 + 1) & 1) * BUFSZ), (c + 1) * 64);
            cp_commit();
            cp_wait<1>();
        } else {
            cp_wait<0>();
        }
        __syncthreads();

        uint32_t bofs = (uint32_t)(((c - c0) & 1) ? BUFSZ : 0);
        uint32_t a_hi = aHi0 + bofs, a_lo = aLo0 + bofs;
        uint32_t b_hi = bHi0 + bofs, b_lo = bLo0 + bofs;

        #pragma unroll
        for (int ks = 0; ks < 4; ks++) {
            uint32_t afh[4][4], bfh[4][4];
            LDM4(afh, a_hi + aoff[ks]);
            LDM4(bfh, b_hi + boff[ks]);
            #pragma unroll
            for (int mf = 0; mf < 4; mf++)
                #pragma unroll
                for (int nf = 0; nf < 8; nf++)
                    mma16816(acc[mf][nf], afh[mf],
                             bfh[nf >> 1][nf & 1], bfh[nf >> 1][(nf & 1) + 2]);
            {
                uint32_t bfl[4][4];
                LDM4(bfl, b_lo + boff[ks]);
                #pragma unroll
                for (int mf = 0; mf < 4; mf++)
                    #pragma unroll
                    for (int nf = 0; nf < 8; nf++)
                        mma16816(acc[mf][nf], afh[mf],
                                 bfl[nf >> 1][nf & 1], bfl[nf >> 1][(nf & 1) + 2]);
            }
            {
                uint32_t afl[4][4];
                LDM4(afl, a_lo + aoff[ks]);
                #pragma unroll
                for (int mf = 0; mf < 4; mf++)
                    #pragma unroll
                    for (int nf = 0; nf < 8; nf++)
                        mma16816(acc[mf][nf], afl[mf],
                                 bfh[nf >> 1][nf & 1], bfh[nf >> 1][(nf & 1) + 2]);
            }
        }
        __syncthreads();
    }

    int r0 = lane >> 2, cb = (lane & 3) * 2;
    if (PARTIAL) {
        float* Cp = C + (size_t)blockIdx.z * M * N;
        #pragma unroll
        for (int mf = 0; mf < 4; mf++)
            #pragma unroll
            for (int nf = 0; nf < 8; nf++) {
                int n0 = bn + wn * 64 + nf * 8 + cb;
                #pragma unroll
                for (int half = 0; half < 2; half++) {
                    int m0 = bm + wm * 64 + mf * 16 + r0 + half * 8;
                    *(float2*)(Cp + (size_t)m0 * N + n0) =
                        make_float2(acc[mf][nf][half * 2], acc[mf][nf][half * 2 + 1]);
                }
            }
        return;
    }
    #pragma unroll
    for (int mf = 0; mf < 4; mf++) {
        #pragma unroll
        for (int nf = 0; nf < 8; nf++) {
            int n0 = bn + wn * 64 + nf * 8 + cb;
            float bz0 = bias ? bias[n0]     : 0.f;
            float bz1 = bias ? bias[n0 + 1] : 0.f;
            #pragma unroll
            for (int half = 0; half < 2; half++) {
                int m0 = bm + wm * 64 + mf * 16 + r0 + half * 8;
                float v0 = acc[mf][nf][half * 2]     + bz0;
                float v1 = acc[mf][nf][half * 2 + 1] + bz1;
                if (ROPE) {
                    if (n0 < 2*DIM) {
                        int pos = m0 & (NTOK - 1);
                        int d   = n0 & (HD - 1);
                        const float* e = remb + pos * (2*HD);
                        float2 sn = *(const float2*)(e + d);
                        float2 cs = *(const float2*)(e + HD + d);
                        float t0 = v0 * cs.x - v1 * sn.x;
                        float t1 = v1 * cs.y + v0 * sn.y;
                        v0 = t0; v1 = t1;
                    }
                }
                size_t idx = (size_t)m0 * N + n0;
                if (res) { v0 += res[idx]; v1 += res[idx + 1]; }
                *(float2*)(C + idx) = make_float2(v0, v1);
            }
        }
    }
}

/* ------------------------------------------------------------------ */
/* reduce3: h += bias + p0 + p1 + p2                                   */
/* ------------------------------------------------------------------ */
__global__ void reduce3(float* __restrict__ h, const float* __restrict__ part,
                        const float* __restrict__ bias) {
    int i = blockIdx.x * blockDim.x + threadIdx.x;
    if (i >= TOKENS*DIM/4) return;
    float4 a  = ((const float4*)h)[i];
    float4 p0 = ((const float4*)part)[i];
    float4 p1 = ((const float4*)(part + TOKENS*DIM))[i];
    float4 p2 = ((const float4*)(part + 2*TOKENS*DIM))[i];
    float4 bz = *(const float4*)(bias + (i*4) % DIM);
    a.x += bz.x + ((p0.x + p1.x) + p2.x);
    a.y += bz.y + ((p0.y + p1.y) + p2.y);
    a.z += bz.z + ((p0.z + p1.z) + p2.z);
    a.w += bz.w + ((p0.w + p1.w) + p2.w);
    ((float4*)h)[i] = a;
}

/* ------------------------------------------------------------------ */
/* Single fused fp32 -> (hi, lo) split+pack for ALL weights            */
/* ------------------------------------------------------------------ */
struct CvtArgs {
    const float* src[7];
    __half* hi[7];
    __half* lo[7];
    int lr[7];
    int ltot[7];
    int off[7];
    int cum[8];
};
__device__ __forceinline__ void split2(float a, float b, __half2& h, __half2& l) {
    __half ha = __float2half_rn(a), hb = __float2half_rn(b);
    __half la = __float2half_rn(a - __half2float(ha));
    __half lb = __float2half_rn(b - __half2float(hb));
    h = __halves2half2(ha, hb);
    l = __halves2half2(la, lb);
}
__global__ void cvt_all(CvtArgs a, int total4) {
    int i4 = blockIdx.x * blockDim.x + threadIdx.x;
    if (i4 >= total4) return;
    int s = 0;
    #pragma unroll
    for (int j = 1; j < 7; j++) s += (i4 >= a.cum[j]);
    int i = (i4 - a.cum[s]) * 4;
    int l = i / a.lr[s];
    int rem = i - l * a.lr[s];
    size_t d = (size_t)l * a.ltot[s] + a.off[s] + rem;
    float4 v = *(const float4*)(a.src[s] + i);
    __half2 h0, l0, h1, l1;
    split2(v.x, v.y, h0, l0);
    split2(v.z, v.w, h1, l1);
    ((__half2*)(a.hi[s] + d))[0] = h0; ((__half2*)(a.hi[s] + d))[1] = h1;
    ((__half2*)(a.lo[s] + d))[0] = l0; ((__half2*)(a.lo[s] + d))[1] = l1;
}

/* ------------------------------------------------------------------ */
/* add_pos + bias packing fused                                        */
/* ------------------------------------------------------------------ */
__global__ void add_pos_prep(const float* __restrict__ x,
                             const float* __restrict__ pos,
                             float* __restrict__ h,
                             const float* __restrict__ bq,
                             const float* __restrict__ bv,
                             float* __restrict__ bqkv,
                             const float* __restrict__ bg,
                             const float* __restrict__ bx,
                             float* __restrict__ b1) {
    int idx = blockIdx.x * blockDim.x + threadIdx.x;
    if (idx < TOKENS*DIM) h[idx] = x[idx] + pos[idx % (NTOK*DIM)];
    if (idx < DEPTH*QS) {
        int l = idx / QS, c = idx % QS;
        bqkv[idx] = c < DIM ? bq[l*DIM + c]
                  : (c < 2*DIM ? 0.f : bv[l*DIM + c - 2*DIM]);
    }
    if (idx < DEPTH*GUS) {
        int l = idx / GUS, c = idx % GUS;
        b1[idx] = c < HIDDEN ? bg[l*HIDDEN + c] : bx[l*HIDDEN + c - HIDDEN];
    }
}

/* ------------------------------------------------------------------ */
/* Block reduction (256 threads)                                       */
/* ------------------------------------------------------------------ */
__device__ __forceinline__ float2 block_reduce_2(float s, float s2) {
    __shared__ float red[16];
    #pragma unroll
    for (int o = 16; o > 0; o >>= 1) {
        s  += __shfl_down_sync(0xffffffffu, s,  o);
        s2 += __shfl_down_sync(0xffffffffu, s2, o);
    }
    int w = threadIdx.x >> 5, l = threadIdx.x & 31;
    if (l == 0) { red[w] = s; red[8 + w] = s2; }
    __syncthreads();
    if (threadIdx.x < 32) {
        s  = (l < 8) ? red[l]     : 0.f;
        s2 = (l < 8) ? red[8 + l] : 0.f;
        #pragma unroll
        for (int o = 4; o > 0; o >>= 1) {
            s  += __shfl_down_sync(0xffffffffu, s,  o);
            s2 += __shfl_down_sync(0xffffffffu, s2, o);
        }
        if (l == 0) { red[0] = s; red[1] = s2; }
    }
    __syncthreads();
    return make_float2(red[0], red[1]);
}

__device__ __forceinline__ uint32_t pack_h2(float a, float b) {
    __half2 h = __floats2half2_rn(a, b);
    return *(uint32_t*)&h;
}

/* ------------------------------------------------------------------ */
/* LayerNorm over DIM (vectorized)                                     */
/* ------------------------------------------------------------------ */
__global__ void __launch_bounds__(256) ln_kernel(
    const float* __restrict__ x, const float* __restrict__ w,
    const float* __restrict__ b, __half* __restrict__ ohi,
    __half* __restrict__ olo) {
    int t = blockIdx.x;
    int c4 = threadIdx.x;
    float4 v = make_float4(0.f, 0.f, 0.f, 0.f);
    if (c4 < DIM/4) v = ((const float4*)(x + (size_t)t * DIM))[c4];
    float s  = v.x + v.y + v.z + v.w;
    float s2 = v.x*v.x + v.y*v.y + v.z*v.z + v.w*v.w;
    float2 r = block_reduce_2(s, s2);
    float mean = r.x / DIM;
    float var  = r.y / DIM - mean * mean;
    float inv  = rsqrtf(var + EPSF);
    if (c4 < DIM/4) {
        float4 wv = ((const float4*)w)[c4];
        float4 bv = ((const float4*)b)[c4];
        float y0 = (v.x - mean) * inv * wv.x + bv.x;
        float y1 = (v.y - mean) * inv * wv.y + bv.y;
        float y2 = (v.z - mean) * inv * wv.z + bv.z;
        float y3 = (v.w - mean) * inv * wv.w + bv.w;
        __half h0 = __float2half_rn(y0), h1 = __float2half_rn(y1);
        __half h2 = __float2half_rn(y2), h3 = __float2half_rn(y3);
        uint2 hi = make_uint2(pack_h2(y0, y1), pack_h2(y2, y3));
        uint2 lo = make_uint2(pack_h2(y0 - __half2float(h0), y1 - __half2float(h1)),
                              pack_h2(y2 - __half2float(h2), y3 - __half2float(h3)));
        ((uint2*)ohi)[(size_t)t * (DIM/4) + c4] = hi;
        ((uint2*)olo)[(size_t)t * (DIM/4) + c4] = lo;
    }
}

/* ------------------------------------------------------------------ */
/* silu(g)*u then LN over HIDDEN (register-resident)                   */
/* ------------------------------------------------------------------ */
__global__ void __launch_bounds__(256) mlp_act_ln_kernel(
    const float* __restrict__ gu,
    const float* __restrict__ w, const float* __restrict__ b,
    __half* __restrict__ ohi, __half* __restrict__ olo) {
    int t = blockIdx.x;
    const float* gr = gu + (size_t)t * GUS;
    const float* ur = gr + HIDDEN;
    float a[8];
    float s = 0.f, s2 = 0.f;
    #pragma unroll
    for (int j = 0; j < 2; j++) {
        int c4 = threadIdx.x + j * 256;
        float4 gv = ((const float4*)gr)[c4];
        float4 uv = ((const float4*)ur)[c4];
        float* aj = a + j * 4;
        aj[0] = gv.x / (1.f + __expf(-gv.x)) * uv.x;
        aj[1] = gv.y / (1.f + __expf(-gv.y)) * uv.y;
        aj[2] = gv.z / (1.f + __expf(-gv.z)) * uv.z;
        aj[3] = gv.w / (1.f + __expf(-gv.w)) * uv.w;
        s  += aj[0] + aj[1] + aj[2] + aj[3];
        s2 += aj[0]*aj[0] + aj[1]*aj[1] + aj[2]*aj[2] + aj[3]*aj[3];
    }
    float2 r = block_reduce_2(s, s2);
    float mean = r.x / HIDDEN;
    float var  = r.y / HIDDEN - mean * mean;
    float inv  = rsqrtf(var + EPSF);
    #pragma unroll
    for (int j = 0; j < 2; j++) {
        int c4 = threadIdx.x + j * 256;
        float4 wv = ((const float4*)w)[c4];
        float4 bv = ((const float4*)b)[c4];
        float* aj = a + j * 4;
        float y0 = (aj[0] - mean) * inv * wv.x + bv.x;
        float y1 = (aj[1] - mean) * inv * wv.y + bv.y;
        float y2 = (aj[2] - mean) * inv * wv.z + bv.z;
        float y3 = (aj[3] - mean) * inv * wv.w + bv.w;
        __half h0 = __float2half_rn(y0), h1 = __float2half_rn(y1);
        __half h2 = __float2half_rn(y2), h3 = __float2half_rn(y3);
        uint2 hi = make_uint2(pack_h2(y0, y1), pack_h2(y2, y3));
        uint2 lo = make_uint2(pack_h2(y0 - __half2float(h0), y1 - __half2float(h1)),
                              pack_h2(y2 - __half2float(h2), y3 - __half2float(h3)));
        ((uint2*)ohi)[(size_t)t * (HIDDEN/4) + c4] = hi;
        ((uint2*)olo)[(size_t)t * (HIDDEN/4) + c4] = lo;
    }
}

/* ------------------------------------------------------------------ */
/* Attention: 2 queries per thread, quad-strided dim slices.           */
/* Thread (g = tid&3, qb = tid>>2) owns dims {k4*16 + g*4 + e} and     */
/* queries {half*128 + qb, +64}. Quad LDS wavefronts are contiguous    */
/* 64B -> conflict/broadcast free. Dot finished by 2 shfl_xor.         */
/* ------------------------------------------------------------------ */
#define KVT 128
#define ATTN_SMEM (2*KVT*HD*4)    /* 65536 */
__global__ void __launch_bounds__(256) attn_kernel(
    const float* __restrict__ qkv, __half* __restrict__ ohi,
    __half* __restrict__ olo) {
    extern __shared__ float sm[];
    float* Ks = sm;                 /* [KVT][64] */
    float* Vs = sm + KVT * HD;
    int blk = blockIdx.x;
    int half_blk = blk & 1;
    int bh = blk >> 1;
    int b  = bh / HEADS, h = bh % HEADS;
    size_t base = (size_t)(b * NTOK) * QS + h * HD;
    int tid = threadIdx.x;
    int g  = tid & 3;               /* quad lane: strided float4 slice  */
    int qb = tid >> 2;              /* 0..63 query slot                  */
    const float scale = 0.125f;

    float qreg[2][16], accv[2][16], mrun[2], lrun[2];
    #pragma unroll
    for (int r = 0; r < 2; r++) {
        int q = half_blk * 128 + qb + 64 * r;
        const float* qp = qkv + base + (size_t)q * QS;
        #pragma unroll
        for (int k4 = 0; k4 < 4; k4++) {
            float4 v = *(const float4*)(qp + k4 * 16 + g * 4);
            qreg[r][k4*4+0] = v.x * scale;
            qreg[r][k4*4+1] = v.y * scale;
            qreg[r][k4*4+2] = v.z * scale;
            qreg[r][k4*4+3] = v.w * scale;
        }
        mrun[r] = -1e30f; lrun[r] = 0.f;
        #pragma unroll
        for (int d = 0; d < 16; d++) accv[r][d] = 0.f;
    }

    for (int tkv = 0; tkv < NTOK / KVT; tkv++) {
        for (int i4 = tid; i4 < KVT * HD / 4; i4 += 256) {
            int row = i4 >> 4, c4 = i4 & 15;
            size_t src = base + (size_t)(tkv * KVT + row) * QS;
            ((float4*)Ks)[i4] = *(const float4*)(qkv + src + DIM   + c4 * 4);
            ((float4*)Vs)[i4] = *(const float4*)(qkv + src + 2*DIM + c4 * 4);
        }
        __syncthreads();

        for (int j = 0; j < KVT; j++) {
            float k[16], v[16];
            const float* kr = Ks + j * HD;
            const float* vr = Vs + j * HD;
            #pragma unroll
            for (int k4 = 0; k4 < 4; k4++) {
                float4 t = *(const float4*)(kr + k4 * 16 + g * 4);
                k[k4*4+0]=t.x; k[k4*4+1]=t.y; k[k4*4+2]=t.z; k[k4*4+3]=t.w;
                float4 u = *(const float4*)(vr + k4 * 16 + g * 4);
                v[k4*4+0]=u.x; v[k4*4+1]=u.y; v[k4*4+2]=u.z; v[k4*4+3]=u.w;
            }
            #pragma unroll
            for (int r = 0; r < 2; r++) {
                float s = 0.f;
                #pragma unroll
                for (int d = 0; d < 16; d++) s += qreg[r][d] * k[d];
                s += __shfl_xor_sync(0xffffffffu, s, 1);
                s += __shfl_xor_sync(0xffffffffu, s, 2);
                float mnew = fmaxf(mrun[r], s);
                float cc = __expf(mrun[r] - mnew);
                float p  = __expf(s - mnew);
                lrun[r] = lrun[r] * cc + p;
                #pragma unroll
                for (int d = 0; d < 16; d++)
                    accv[r][d] = accv[r][d] * cc + p * v[d];
                mrun[r] = mnew;
            }
        }
        __syncthreads();
    }

    #pragma unroll
    for (int r = 0; r < 2; r++) {
        float inv = 1.f / lrun[r];
        int q = half_blk * 128 + qb + 64 * r;
        size_t ob = (size_t)(b * NTOK + q) * DIM + h * HD;
        #pragma unroll
        for (int k4 = 0; k4 < 4; k4++) {
            float y0 = accv[r][k4*4+0] * inv;
            float y1 = accv[r][k4*4+1] * inv;
            float y2 = accv[r][k4*4+2] * inv;
            float y3 = accv[r][k4*4+3] * inv;
            __half h0 = __float2half_rn(y0), h1 = __float2half_rn(y1);
            __half h2 = __float2half_rn(y2), h3 = __float2half_rn(y3);
            uint2 hi = make_uint2(pack_h2(y0, y1), pack_h2(y2, y3));
            uint2 lo = make_uint2(
                pack_h2(y0 - __half2float(h0), y1 - __half2float(h1)),
                pack_h2(y2 - __half2float(h2), y3 - __half2float(h3)));
            *(uint2*)(ohi + ob + k4 * 16 + g * 4) = hi;
            *(uint2*)(olo + ob + k4 * 16 + g * 4) = lo;
        }
    }
}

/* ------------------------------------------------------------------ */
/* Launch                                                              */
/* ------------------------------------------------------------------ */
extern "C" void kernel_launch(void* const* d_in, const int* in_sizes, int n_in,
                              void* d_out, int out_size) {
    const float* x      = (const float*)d_in[0];
    const float* pos    = (const float*)d_in[1];
    const float* rope   = (const float*)d_in[2];
    const float* ln1_w  = (const float*)d_in[3];
    const float* ln1_b  = (const float*)d_in[4];
    const float* wq     = (const float*)d_in[5];
    const float* bq     = (const float*)d_in[6];
    const float* wk     = (const float*)d_in[7];
    const float* wv     = (const float*)d_in[8];
    const float* bv     = (const float*)d_in[9];
    const float* wo     = (const float*)d_in[10];
    const float* bo     = (const float*)d_in[11];
    const float* ln2_w  = (const float*)d_in[12];
    const float* ln2_b  = (const float*)d_in[13];
    const float* w1g    = (const float*)d_in[14];
    const float* b1g    = (const float*)d_in[15];
    const float* w1x    = (const float*)d_in[16];
    const float* b1x    = (const float*)d_in[17];
    const float* lnm_w  = (const float*)d_in[18];
    const float* lnm_b  = (const float*)d_in[19];
    const float* w2     = (const float*)d_in[20];
    const float* b2     = (const float*)d_in[21];
    float* h = (float*)d_out;

    float *qkv, *gu, *bqkv, *b1, *part;
    __half *yhh, *yhl, *ohh, *ohl, *mhh, *mhl;
    __half *wqkvh, *wqkvl, *woh, *wol, *w1h, *w1l, *w2h, *w2l;
    cudaGetSymbolAddress((void**)&qkv,   g_qkv);
    cudaGetSymbolAddress((void**)&gu,    g_gu);
    cudaGetSymbolAddress((void**)&part,  g_part);
    cudaGetSymbolAddress((void**)&bqkv,  g_bqkv);
    cudaGetSymbolAddress((void**)&b1,    g_b1);
    cudaGetSymbolAddress((void**)&yhh,   g_yh_hi);
    cudaGetSymbolAddress((void**)&yhl,   g_yh_lo);
    cudaGetSymbolAddress((void**)&ohh,   g_oh_hi);
    cudaGetSymbolAddress((void**)&ohl,   g_oh_lo);
    cudaGetSymbolAddress((void**)&mhh,   g_mh_hi);
    cudaGetSymbolAddress((void**)&mhl,   g_mh_lo);
    cudaGetSymbolAddress((void**)&wqkvh, g_wqkv_hi);
    cudaGetSymbolAddress((void**)&wqkvl, g_wqkv_lo);
    cudaGetSymbolAddress((void**)&woh,   g_wo_hi);
    cudaGetSymbolAddress((void**)&wol,   g_wo_lo);
    cudaGetSymbolAddress((void**)&w1h,   g_w1_hi);
    cudaGetSymbolAddress((void**)&w1l,   g_w1_lo);
    cudaGetSymbolAddress((void**)&w2h,   g_w2_hi);
    cudaGetSymbolAddress((void**)&w2l,   g_w2_lo);

    cudaFuncSetAttribute((const void*)gemm_mma<true,false>,
                         cudaFuncAttributeMaxDynamicSharedMemorySize, GEMM_SMEM);
    cudaFuncSetAttribute((const void*)gemm_mma<false,false>,
                         cudaFuncAttributeMaxDynamicSharedMemorySize, GEMM_SMEM);
    cudaFuncSetAttribute((const void*)gemm_mma<false,true>,
                         cudaFuncAttributeMaxDynamicSharedMemorySize, GEMM_SMEM);
    cudaFuncSetAttribute((const void*)attn_kernel,
                         cudaFuncAttributeMaxDynamicSharedMemorySize, ATTN_SMEM);

    /* ---- [1] fused weight split + pack ---- */
    {
        const int nD = DIM*DIM, nH = HIDDEN*DIM;
        CvtArgs a;
        const float* srcs[7] = { wq, wk, wv, wo, w1g, w1x, w2 };
        __half* his[7] = { wqkvh, wqkvh, wqkvh, woh, w1h, w1h, w2h };
        __half* los[7] = { wqkvl, wqkvl, wqkvl, wol, w1l, w1l, w2l };
        int lrs[7]   = { nD, nD, nD, nD, nH, nH, nH };
        int ltots[7] = { QS*DIM, QS*DIM, QS*DIM, nD, GUS*DIM, GUS*DIM, nH };
        int offs[7]  = { 0, nD, 2*nD, 0, 0, nH, 0 };
        int cum = 0;
        for (int s = 0; s < 7; s++) {
            a.src[s] = srcs[s]; a.hi[s] = his[s]; a.lo[s] = los[s];
            a.lr[s] = lrs[s]; a.ltot[s] = ltots[s]; a.off[s] = offs[s];
            a.cum[s] = cum;
            cum += DEPTH * lrs[s] / 4;
        }
        a.cum[7] = cum;
        cvt_all<<<(cum + 255)/256, 256>>>(a, cum);
    }
    /* ---- [2] pos-embed add + bias packing ---- */
    add_pos_prep<<<(TOKENS*DIM + 255)/256, 256>>>(x, pos, h, bq, bv, bqkv,
                                                  b1g, b1x, b1);

    dim3 gQKV(QS/256,  TOKENS/128);      /* (9, 32)    */
    dim3 gMLP(GUS/256, TOKENS/128);      /* (16, 32)   */
    dim3 gSK (DIM/256, TOKENS/128, 3);   /* (3, 32, 3) */
    const int RED = (TOKENS*DIM/4 + 255)/256;

    for (int l = 0; l < DEPTH; l++) {
        size_t oqkv = (size_t)l * QS * DIM;
        size_t owo  = (size_t)l * DIM * DIM;
        size_t ow1  = (size_t)l * GUS * DIM;
        size_t ow2  = (size_t)l * DIM * HIDDEN;

        /* ---- attention ---- */
        ln_kernel<<<TOKENS, 256>>>(h, ln1_w + l*DIM, ln1_b + l*DIM, yhh, yhl);
        gemm_mma<true,false><<<gQKV, 256, GEMM_SMEM>>>(
            yhh, yhl, wqkvh + oqkv, wqkvl + oqkv,
            bqkv + l*QS, nullptr, qkv, rope, TOKENS, QS, DIM);
        attn_kernel<<<BATCH*HEADS*2, 256, ATTN_SMEM>>>(qkv, ohh, ohl);
        gemm_mma<false,true><<<gSK, 256, GEMM_SMEM>>>(
            ohh, ohl, woh + owo, wol + owo,
            nullptr, nullptr, part, nullptr, TOKENS, DIM, DIM);
        reduce3<<<RED, 256>>>(h, part, bo + l*DIM);

        /* ---- SwiGLU MLP ---- */
        ln_kernel<<<TOKENS, 256>>>(h, ln2_w + l*DIM, ln2_b + l*DIM, yhh, yhl);
        gemm_mma<false,false><<<gMLP, 256, GEMM_SMEM>>>(
            yhh, yhl, w1h + ow1, w1l + ow1,
            b1 + l*GUS, nullptr, gu, nullptr, TOKENS, GUS, DIM);
        mlp_act_ln_kernel<<<TOKENS, 256>>>(gu, lnm_w + l*HIDDEN, lnm_b + l*HIDDEN, mhh, mhl);
        gemm_mma<false,true><<<gSK, 256, GEMM_SMEM>>>(
            mhh, mhl, w2h + ow2, w2l + ow2,
            nullptr, nullptr, part, nullptr, TOKENS, DIM, HIDDEN);
        reduce3<<<RED, 256>>>(h, part, b2 + l*DIM);
    }
}

// round 14
// speedup vs baseline: 1.8464x; 1.0209x over previous
#include <cuda_runtime.h>
#include <cuda_fp16.h>
#include <math.h>
#include <stdint.h>

#define DEPTH   12
#define BATCH   16
#define NTOK    256
#define TOKENS  (BATCH*NTOK)     /* 4096 */
#define DIM     768
#define HEADS   12
#define HD      64
#define HIDDEN  2048
#define EPSF    1e-5f
#define QS      2304             /* packed qkv row stride */
#define GUS     4096             /* packed g|u row stride */

/* ------------------------------------------------------------------ */
/* Scratch buffers                                                     */
/* ------------------------------------------------------------------ */
__device__ float  g_qkv[TOKENS*QS];
__device__ float  g_gu[TOKENS*GUS];
__device__ float  g_part[3*TOKENS*DIM];
__device__ __half g_yh_hi[TOKENS*DIM];
__device__ __half g_yh_lo[TOKENS*DIM];
__device__ __half g_oh_hi[TOKENS*DIM];
__device__ __half g_oh_lo[TOKENS*DIM];
__device__ __half g_mh_hi[TOKENS*HIDDEN];
__device__ __half g_mh_lo[TOKENS*HIDDEN];

/* packed split weights */
__device__ __half g_wqkv_hi[DEPTH*QS*DIM];
__device__ __half g_wqkv_lo[DEPTH*QS*DIM];
__device__ __half g_wo_hi[DEPTH*DIM*DIM];
__device__ __half g_wo_lo[DEPTH*DIM*DIM];
__device__ __half g_w1_hi[DEPTH*GUS*DIM];
__device__ __half g_w1_lo[DEPTH*GUS*DIM];
__device__ __half g_w2_hi[DEPTH*DIM*HIDDEN];
__device__ __half g_w2_lo[DEPTH*DIM*HIDDEN];
__device__ float  g_bqkv[DEPTH*QS];
__device__ float  g_b1[DEPTH*GUS];

/* ------------------------------------------------------------------ */
/* PTX helpers                                                         */
/* ------------------------------------------------------------------ */
__device__ __forceinline__ uint32_t smem_u32(const void* p) {
    uint32_t a;
    asm("{ .reg .u64 t; cvta.to.shared.u64 t, %1; cvt.u32.u64 %0, t; }"
        : "=r"(a) : "l"(p));
    return a;
}
__device__ __forceinline__ void cp16(uint32_t dst, const void* src) {
    asm volatile("cp.async.cg.shared.global [%0], [%1], 16;"
                 :: "r"(dst), "l"(src) : "memory");
}
__device__ __forceinline__ void cp_commit() {
    asm volatile("cp.async.commit_group;" ::: "memory");
}
template<int NWAIT>
__device__ __forceinline__ void cp_wait() {
    asm volatile("cp.async.wait_group %0;" :: "n"(NWAIT) : "memory");
}
template<int IMM>
__device__ __forceinline__ void ldmx4i(uint32_t& r0, uint32_t& r1,
                                       uint32_t& r2, uint32_t& r3, uint32_t a) {
    asm volatile("ldmatrix.sync.aligned.m8n8.x4.shared.b16 {%0,%1,%2,%3}, [%4+%5];"
                 : "=r"(r0), "=r"(r1), "=r"(r2), "=r"(r3) : "r"(a), "n"(IMM));
}
#define LDM4(f, base) do {                                        \
    ldmx4i<0>   ((f)[0][0], (f)[0][1], (f)[0][2], (f)[0][3], base); \
    ldmx4i<2048>((f)[1][0], (f)[1][1], (f)[1][2], (f)[1][3], base); \
    ldmx4i<4096>((f)[2][0], (f)[2][1], (f)[2][2], (f)[2][3], base); \
    ldmx4i<6144>((f)[3][0], (f)[3][1], (f)[3][2], (f)[3][3], base); \
} while (0)

__device__ __forceinline__ void mma16816(float* c, const uint32_t* a,
                                         uint32_t b0, uint32_t b1) {
    asm("mma.sync.aligned.m16n8k16.row.col.f32.f16.f16.f32 "
        "{%0,%1,%2,%3}, {%4,%5,%6,%7}, {%8,%9}, {%0,%1,%2,%3};"
        : "+f"(c[0]), "+f"(c[1]), "+f"(c[2]), "+f"(c[3])
        : "r"(a[0]), "r"(a[1]), "r"(a[2]), "r"(a[3]), "r"(b0), "r"(b1));
}

/* ------------------------------------------------------------------ */
/* Split-fp16 HMMA GEMM (NT): C = Ahi*Bhi + Ahi*Blo + Alo*Bhi          */
/* CTA tile 128x256, 8 warps of 64x64 (2x4), BK=64, double-buffered.   */
/* ------------------------------------------------------------------ */
#define PA 16384
#define PB 32768
#define BUFSZ (2*PA + 2*PB)            /* 98304 */
#define GEMM_SMEM (2*BUFSZ)            /* 196608 */

template<bool ROPE, bool PARTIAL>
__global__ void __launch_bounds__(256, 1) gemm_mma(
    const __half* __restrict__ Ahi, const __half* __restrict__ Alo,
    const __half* __restrict__ Bhi, const __half* __restrict__ Blo,
    const float* __restrict__ bias, const float* __restrict__ res,
    float* __restrict__ C, const float* __restrict__ remb,
    int M, int N, int K) {
    extern __shared__ __align__(128) char smem[];
    uint32_t sb = smem_u32(smem);
    int tid = threadIdx.x, wid = tid >> 5, lane = tid & 31;
    int wm = wid >> 2, wn = wid & 3;
    int bm = blockIdx.y * 128, bn = blockIdx.x * 256;

    int l15 = lane & 15, kg = lane >> 4;
    uint32_t arow = (uint32_t)(wm * 64 + l15);
    uint32_t brow = (uint32_t)(wn * 64 + l15);
    int aswz = (int)(arow & 7), bswz = (int)(brow & 7);

    uint32_t aoff[4], boff[4];
    #pragma unroll
    for (int ks = 0; ks < 4; ks++) {
        int g = ks * 2 + kg;
        aoff[ks] = (uint32_t)((g ^ aswz) * 16);
        boff[ks] = (uint32_t)((g ^ bswz) * 16);
    }
    uint32_t aHi0 = sb             + arow * 128u;
    uint32_t aLo0 = sb + PA        + arow * 128u;
    uint32_t bHi0 = sb + 2*PA      + brow * 128u;
    uint32_t bLo0 = sb + 2*PA + PB + brow * 128u;

    float acc[4][8][4];
    #pragma unroll
    for (int i = 0; i < 4; i++)
        #pragma unroll
        for (int j = 0; j < 8; j++)
            #pragma unroll
            for (int e = 0; e < 4; e++) acc[i][j][e] = 0.f;

    int nch = K >> 6;
    int c0 = 0, c1 = nch;
    if (PARTIAL) {
        int z = blockIdx.z;
        c0 = (z * nch) / 3;
        c1 = ((z + 1) * nch) / 3;
    }

    auto load_chunk = [&](uint32_t dst, int ko) {
        #pragma unroll
        for (int j = 0; j < 4; j++) {
            int id = tid + j * 256;
            int row = id >> 3, g = id & 7;
            uint32_t off = (uint32_t)row * 128u + (uint32_t)((g ^ (row & 7)) * 16);
            size_t so = (size_t)(bm + row) * K + ko + g * 8;
            cp16(dst + off,      Ahi + so);
            cp16(dst + PA + off, Alo + so);
        }
        #pragma unroll
        for (int j = 0; j < 8; j++) {
            int id = tid + j * 256;
            int row = id >> 3, g = id & 7;
            uint32_t off = (uint32_t)row * 128u + (uint32_t)((g ^ (row & 7)) * 16);
            size_t so = (size_t)(bn + row) * K + ko + g * 8;
            cp16(dst + 2*PA + off,      Bhi + so);
            cp16(dst + 2*PA + PB + off, Blo + so);
        }
    };

    load_chunk(sb, c0 * 64);
    cp_commit();

    for (int c = c0; c < c1; c++) {
        if (c + 1 < c1) {
            load_chunk(sb + (uint32_t)(((c - c0 + 1) & 1) * BUFSZ), (c + 1) * 64);
            cp_commit();
            cp_wait<1>();
        } else {
            cp_wait<0>();
        }
        __syncthreads();

        uint32_t bofs = (uint32_t)(((c - c0) & 1) ? BUFSZ : 0);
        uint32_t a_hi = aHi0 + bofs, a_lo = aLo0 + bofs;
        uint32_t b_hi = bHi0 + bofs, b_lo = bLo0 + bofs;

        #pragma unroll
        for (int ks = 0; ks < 4; ks++) {
            uint32_t afh[4][4], bfh[4][4];
            LDM4(afh, a_hi + aoff[ks]);
            LDM4(bfh, b_hi + boff[ks]);
            #pragma unroll
            for (int mf = 0; mf < 4; mf++)
                #pragma unroll
                for (int nf = 0; nf < 8; nf++)
                    mma16816(acc[mf][nf], afh[mf],
                             bfh[nf >> 1][nf & 1], bfh[nf >> 1][(nf & 1) + 2]);
            {
                uint32_t bfl[4][4];
                LDM4(bfl, b_lo + boff[ks]);
                #pragma unroll
                for (int mf = 0; mf < 4; mf++)
                    #pragma unroll
                    for (int nf = 0; nf < 8; nf++)
                        mma16816(acc[mf][nf], afh[mf],
                                 bfl[nf >> 1][nf & 1], bfl[nf >> 1][(nf & 1) + 2]);
            }
            {
                uint32_t afl[4][4];
                LDM4(afl, a_lo + aoff[ks]);
                #pragma unroll
                for (int mf = 0; mf < 4; mf++)
                    #pragma unroll
                    for (int nf = 0; nf < 8; nf++)
                        mma16816(acc[mf][nf], afl[mf],
                                 bfh[nf >> 1][nf & 1], bfh[nf >> 1][(nf & 1) + 2]);
            }
        }
        __syncthreads();
    }

    int r0 = lane >> 2, cb = (lane & 3) * 2;
    if (PARTIAL) {
        float* Cp = C + (size_t)blockIdx.z * M * N;
        #pragma unroll
        for (int mf = 0; mf < 4; mf++)
            #pragma unroll
            for (int nf = 0; nf < 8; nf++) {
                int n0 = bn + wn * 64 + nf * 8 + cb;
                #pragma unroll
                for (int half = 0; half < 2; half++) {
                    int m0 = bm + wm * 64 + mf * 16 + r0 + half * 8;
                    *(float2*)(Cp + (size_t)m0 * N + n0) =
                        make_float2(acc[mf][nf][half * 2], acc[mf][nf][half * 2 + 1]);
                }
            }
        return;
    }
    #pragma unroll
    for (int mf = 0; mf < 4; mf++) {
        #pragma unroll
        for (int nf = 0; nf < 8; nf++) {
            int n0 = bn + wn * 64 + nf * 8 + cb;
            float bz0 = bias ? bias[n0]     : 0.f;
            float bz1 = bias ? bias[n0 + 1] : 0.f;
            #pragma unroll
            for (int half = 0; half < 2; half++) {
                int m0 = bm + wm * 64 + mf * 16 + r0 + half * 8;
                float v0 = acc[mf][nf][half * 2]     + bz0;
                float v1 = acc[mf][nf][half * 2 + 1] + bz1;
                if (ROPE) {
                    if (n0 < 2*DIM) {
                        int pos = m0 & (NTOK - 1);
                        int d   = n0 & (HD - 1);
                        const float* e = remb + pos * (2*HD);
                        float2 sn = *(const float2*)(e + d);
                        float2 cs = *(const float2*)(e + HD + d);
                        float t0 = v0 * cs.x - v1 * sn.x;
                        float t1 = v1 * cs.y + v0 * sn.y;
                        v0 = t0; v1 = t1;
                    }
                }
                size_t idx = (size_t)m0 * N + n0;
                if (res) { v0 += res[idx]; v1 += res[idx + 1]; }
                *(float2*)(C + idx) = make_float2(v0, v1);
            }
        }
    }
}

/* ------------------------------------------------------------------ */
/* reduce3: h += bias + p0 + p1 + p2 (final layer only)                */
/* ------------------------------------------------------------------ */
__global__ void reduce3(float* __restrict__ h, const float* __restrict__ part,
                        const float* __restrict__ bias) {
    int i = blockIdx.x * blockDim.x + threadIdx.x;
    if (i >= TOKENS*DIM/4) return;
    float4 a  = ((const float4*)h)[i];
    float4 p0 = ((const float4*)part)[i];
    float4 p1 = ((const float4*)(part + TOKENS*DIM))[i];
    float4 p2 = ((const float4*)(part + 2*TOKENS*DIM))[i];
    float4 bz = *(const float4*)(bias + (i*4) % DIM);
    a.x += bz.x + ((p0.x + p1.x) + p2.x);
    a.y += bz.y + ((p0.y + p1.y) + p2.y);
    a.z += bz.z + ((p0.z + p1.z) + p2.z);
    a.w += bz.w + ((p0.w + p1.w) + p2.w);
    ((float4*)h)[i] = a;
}

/* ------------------------------------------------------------------ */
/* Single fused fp32 -> (hi, lo) split+pack for ALL weights            */
/* ------------------------------------------------------------------ */
struct CvtArgs {
    const float* src[7];
    __half* hi[7];
    __half* lo[7];
    int lr[7];
    int ltot[7];
    int off[7];
    int cum[8];
};
__device__ __forceinline__ void split2(float a, float b, __half2& h, __half2& l) {
    __half ha = __float2half_rn(a), hb = __float2half_rn(b);
    __half la = __float2half_rn(a - __half2float(ha));
    __half lb = __float2half_rn(b - __half2float(hb));
    h = __halves2half2(ha, hb);
    l = __halves2half2(la, lb);
}
__global__ void cvt_all(CvtArgs a, int total4) {
    int i4 = blockIdx.x * blockDim.x + threadIdx.x;
    if (i4 >= total4) return;
    int s = 0;
    #pragma unroll
    for (int j = 1; j < 7; j++) s += (i4 >= a.cum[j]);
    int i = (i4 - a.cum[s]) * 4;
    int l = i / a.lr[s];
    int rem = i - l * a.lr[s];
    size_t d = (size_t)l * a.ltot[s] + a.off[s] + rem;
    float4 v = *(const float4*)(a.src[s] + i);
    __half2 h0, l0, h1, l1;
    split2(v.x, v.y, h0, l0);
    split2(v.z, v.w, h1, l1);
    ((__half2*)(a.hi[s] + d))[0] = h0; ((__half2*)(a.hi[s] + d))[1] = h1;
    ((__half2*)(a.lo[s] + d))[0] = l0; ((__half2*)(a.lo[s] + d))[1] = l1;
}

/* ------------------------------------------------------------------ */
/* add_pos + bias packing fused                                        */
/* ------------------------------------------------------------------ */
__global__ void add_pos_prep(const float* __restrict__ x,
                             const float* __restrict__ pos,
                             float* __restrict__ h,
                             const float* __restrict__ bq,
                             const float* __restrict__ bv,
                             float* __restrict__ bqkv,
                             const float* __restrict__ bg,
                             const float* __restrict__ bx,
                             float* __restrict__ b1) {
    int idx = blockIdx.x * blockDim.x + threadIdx.x;
    if (idx < TOKENS*DIM) h[idx] = x[idx] + pos[idx % (NTOK*DIM)];
    if (idx < DEPTH*QS) {
        int l = idx / QS, c = idx % QS;
        bqkv[idx] = c < DIM ? bq[l*DIM + c]
                  : (c < 2*DIM ? 0.f : bv[l*DIM + c - 2*DIM]);
    }
    if (idx < DEPTH*GUS) {
        int l = idx / GUS, c = idx % GUS;
        b1[idx] = c < HIDDEN ? bg[l*HIDDEN + c] : bx[l*HIDDEN + c - HIDDEN];
    }
}

/* ------------------------------------------------------------------ */
/* Block reductions (256 threads)                                      */
/* ------------------------------------------------------------------ */
__device__ __forceinline__ float2 block_reduce_2(float s, float s2) {
    __shared__ float red[16];
    #pragma unroll
    for (int o = 16; o > 0; o >>= 1) {
        s  += __shfl_down_sync(0xffffffffu, s,  o);
        s2 += __shfl_down_sync(0xffffffffu, s2, o);
    }
    int w = threadIdx.x >> 5, l = threadIdx.x & 31;
    if (l == 0) { red[w] = s; red[8 + w] = s2; }
    __syncthreads();
    if (threadIdx.x < 32) {
        s  = (l < 8) ? red[l]     : 0.f;
        s2 = (l < 8) ? red[8 + l] : 0.f;
        #pragma unroll
        for (int o = 4; o > 0; o >>= 1) {
            s  += __shfl_down_sync(0xffffffffu, s,  o);
            s2 += __shfl_down_sync(0xffffffffu, s2, o);
        }
        if (l == 0) { red[0] = s; red[1] = s2; }
    }
    __syncthreads();
    return make_float2(red[0], red[1]);
}
__device__ __forceinline__ float block_reduce_max(float m) {
    __shared__ float redm[8];
    #pragma unroll
    for (int o = 16; o > 0; o >>= 1)
        m = fmaxf(m, __shfl_xor_sync(0xffffffffu, m, o));
    int w = threadIdx.x >> 5, l = threadIdx.x & 31;
    if (l == 0) redm[w] = m;
    __syncthreads();
    if (threadIdx.x < 32) {
        m = (l < 8) ? redm[l] : 0.f;
        #pragma unroll
        for (int o = 4; o > 0; o >>= 1)
            m = fmaxf(m, __shfl_xor_sync(0xffffffffu, m, o));
        if (l == 0) redm[0] = m;
    }
    __syncthreads();
    return redm[0];
}

__device__ __forceinline__ uint32_t pack_h2(float a, float b) {
    __half2 h = __floats2half2_rn(a, b);
    return *(uint32_t*)&h;
}

/* ------------------------------------------------------------------ */
/* Fused residual-reduce + LayerNorm over DIM (vectorized)             */
/* If part != null: h += gbias + p0+p1+p2 first (writes h back).       */
/* ------------------------------------------------------------------ */
__global__ void __launch_bounds__(256) ln_fused(
    float* __restrict__ h, const float* __restrict__ part,
    const float* __restrict__ gbias,
    const float* __restrict__ w, const float* __restrict__ b,
    __half* __restrict__ ohi, __half* __restrict__ olo) {
    int t = blockIdx.x;
    int c4 = threadIdx.x;
    size_t i4 = (size_t)t * (DIM/4) + c4;
    float4 v = make_float4(0.f, 0.f, 0.f, 0.f);
    if (c4 < DIM/4) {
        v = ((const float4*)h)[i4];
        if (part) {
            float4 p0 = ((const float4*)part)[i4];
            float4 p1 = ((const float4*)(part + TOKENS*DIM))[i4];
            float4 p2 = ((const float4*)(part + 2*TOKENS*DIM))[i4];
            float4 bz = ((const float4*)gbias)[c4];
            v.x += bz.x + ((p0.x + p1.x) + p2.x);
            v.y += bz.y + ((p0.y + p1.y) + p2.y);
            v.z += bz.z + ((p0.z + p1.z) + p2.z);
            v.w += bz.w + ((p0.w + p1.w) + p2.w);
            ((float4*)h)[i4] = v;
        }
    }
    float s  = v.x + v.y + v.z + v.w;
    float s2 = v.x*v.x + v.y*v.y + v.z*v.z + v.w*v.w;
    float2 r = block_reduce_2(s, s2);
    float mean = r.x / DIM;
    float var  = r.y / DIM - mean * mean;
    float inv  = rsqrtf(var + EPSF);
    if (c4 < DIM/4) {
        float4 wv = ((const float4*)w)[c4];
        float4 bv = ((const float4*)b)[c4];
        float y0 = (v.x - mean) * inv * wv.x + bv.x;
        float y1 = (v.y - mean) * inv * wv.y + bv.y;
        float y2 = (v.z - mean) * inv * wv.z + bv.z;
        float y3 = (v.w - mean) * inv * wv.w + bv.w;
        __half h0 = __float2half_rn(y0), h1 = __float2half_rn(y1);
        __half h2 = __float2half_rn(y2), h3 = __float2half_rn(y3);
        uint2 hi = make_uint2(pack_h2(y0, y1), pack_h2(y2, y3));
        uint2 lo = make_uint2(pack_h2(y0 - __half2float(h0), y1 - __half2float(h1)),
                              pack_h2(y2 - __half2float(h2), y3 - __half2float(h3)));
        ((uint2*)ohi)[i4] = hi;
        ((uint2*)olo)[i4] = lo;
    }
}

/* ------------------------------------------------------------------ */
/* silu(g)*u then LN over HIDDEN (register-resident)                   */
/* ------------------------------------------------------------------ */
__global__ void __launch_bounds__(256) mlp_act_ln_kernel(
    const float* __restrict__ gu,
    const float* __restrict__ w, const float* __restrict__ b,
    __half* __restrict__ ohi, __half* __restrict__ olo) {
    int t = blockIdx.x;
    const float* gr = gu + (size_t)t * GUS;
    const float* ur = gr + HIDDEN;
    float a[8];
    float s = 0.f, s2 = 0.f;
    #pragma unroll
    for (int j = 0; j < 2; j++) {
        int c4 = threadIdx.x + j * 256;
        float4 gv = ((const float4*)gr)[c4];
        float4 uv = ((const float4*)ur)[c4];
        float* aj = a + j * 4;
        aj[0] = gv.x / (1.f + __expf(-gv.x)) * uv.x;
        aj[1] = gv.y / (1.f + __expf(-gv.y)) * uv.y;
        aj[2] = gv.z / (1.f + __expf(-gv.z)) * uv.z;
        aj[3] = gv.w / (1.f + __expf(-gv.w)) * uv.w;
        s  += aj[0] + aj[1] + aj[2] + aj[3];
        s2 += aj[0]*aj[0] + aj[1]*aj[1] + aj[2]*aj[2] + aj[3]*aj[3];
    }
    float2 r = block_reduce_2(s, s2);
    float mean = r.x / HIDDEN;
    float var  = r.y / HIDDEN - mean * mean;
    float inv  = rsqrtf(var + EPSF);
    #pragma unroll
    for (int j = 0; j < 2; j++) {
        int c4 = threadIdx.x + j * 256;
        float4 wv = ((const float4*)w)[c4];
        float4 bv = ((const float4*)b)[c4];
        float* aj = a + j * 4;
        float y0 = (aj[0] - mean) * inv * wv.x + bv.x;
        float y1 = (aj[1] - mean) * inv * wv.y + bv.y;
        float y2 = (aj[2] - mean) * inv * wv.z + bv.z;
        float y3 = (aj[3] - mean) * inv * wv.w + bv.w;
        __half h0 = __float2half_rn(y0), h1 = __float2half_rn(y1);
        __half h2 = __float2half_rn(y2), h3 = __float2half_rn(y3);
        uint2 hi = make_uint2(pack_h2(y0, y1), pack_h2(y2, y3));
        uint2 lo = make_uint2(pack_h2(y0 - __half2float(h0), y1 - __half2float(h1)),
                              pack_h2(y2 - __half2float(h2), y3 - __half2float(h3)));
        ((uint2*)ohi)[(size_t)t * (HIDDEN/4) + c4] = hi;
        ((uint2*)olo)[(size_t)t * (HIDDEN/4) + c4] = lo;
    }
}

/* ------------------------------------------------------------------ */
/* Attention: 2 queries/thread, quad-strided slices, STATIC max bound  */
/* M_q = ||q||*max_k||k|| >= all scores -> no online-max updates.      */
/* ------------------------------------------------------------------ */
#define KVT 128
#define ATTN_SMEM (2*KVT*HD*4)    /* 65536 */
__global__ void __launch_bounds__(256) attn_kernel(
    const float* __restrict__ qkv, __half* __restrict__ ohi,
    __half* __restrict__ olo) {
    extern __shared__ float sm[];
    float* Ks = sm;
    float* Vs = sm + KVT * HD;
    int blk = blockIdx.x;
    int half_blk = blk & 1;
    int bh = blk >> 1;
    int b  = bh / HEADS, h = bh % HEADS;
    size_t base = (size_t)(b * NTOK) * QS + h * HD;
    int tid = threadIdx.x;
    int g  = tid & 3;
    int qb = tid >> 2;
    const float scale = 0.125f;

    /* ---- key-norm pre-pass: kmax = max_j ||k_j|| (1 key/thread) ---- */
    float km2 = 0.f;
    {
        const float* kp = qkv + base + (size_t)tid * QS + DIM;
        #pragma unroll 4
        for (int c4 = 0; c4 < 16; c4++) {
            float4 t = *(const float4*)(kp + c4 * 4);
            km2 += t.x*t.x + t.y*t.y + t.z*t.z + t.w*t.w;
        }
    }
    float kmax = sqrtf(block_reduce_max(km2));

    float qreg[2][16], accv[2][16], lrun[2], Mq[2];
    #pragma unroll
    for (int r = 0; r < 2; r++) {
        int q = half_blk * 128 + qb + 64 * r;
        const float* qp = qkv + base + (size_t)q * QS;
        float qn2 = 0.f;
        #pragma unroll
        for (int k4 = 0; k4 < 4; k4++) {
            float4 v = *(const float4*)(qp + k4 * 16 + g * 4);
            qreg[r][k4*4+0] = v.x * scale;
            qreg[r][k4*4+1] = v.y * scale;
            qreg[r][k4*4+2] = v.z * scale;
            qreg[r][k4*4+3] = v.w * scale;
            qn2 += qreg[r][k4*4+0]*qreg[r][k4*4+0] + qreg[r][k4*4+1]*qreg[r][k4*4+1]
                 + qreg[r][k4*4+2]*qreg[r][k4*4+2] + qreg[r][k4*4+3]*qreg[r][k4*4+3];
        }
        qn2 += __shfl_xor_sync(0xffffffffu, qn2, 1);
        qn2 += __shfl_xor_sync(0xffffffffu, qn2, 2);
        Mq[r] = sqrtf(qn2) * kmax;
        lrun[r] = 0.f;
        #pragma unroll
        for (int d = 0; d < 16; d++) accv[r][d] = 0.f;
    }

    for (int tkv = 0; tkv < NTOK / KVT; tkv++) {
        for (int i4 = tid; i4 < KVT * HD / 4; i4 += 256) {
            int row = i4 >> 4, c4 = i4 & 15;
            size_t src = base + (size_t)(tkv * KVT + row) * QS;
            ((float4*)Ks)[i4] = *(const float4*)(qkv + src + DIM   + c4 * 4);
            ((float4*)Vs)[i4] = *(const float4*)(qkv + src + 2*DIM + c4 * 4);
        }
        __syncthreads();

        for (int j = 0; j < KVT; j++) {
            float k[16], v[16];
            const float* kr = Ks + j * HD;
            const float* vr = Vs + j * HD;
            #pragma unroll
            for (int k4 = 0; k4 < 4; k4++) {
                float4 t = *(const float4*)(kr + k4 * 16 + g * 4);
                k[k4*4+0]=t.x; k[k4*4+1]=t.y; k[k4*4+2]=t.z; k[k4*4+3]=t.w;
                float4 u = *(const float4*)(vr + k4 * 16 + g * 4);
                v[k4*4+0]=u.x; v[k4*4+1]=u.y; v[k4*4+2]=u.z; v[k4*4+3]=u.w;
            }
            #pragma unroll
            for (int r = 0; r < 2; r++) {
                float s = 0.f;
                #pragma unroll
                for (int d = 0; d < 16; d++) s += qreg[r][d] * k[d];
                s += __shfl_xor_sync(0xffffffffu, s, 1);
                s += __shfl_xor_sync(0xffffffffu, s, 2);
                float p = __expf(s - Mq[r]);
                lrun[r] += p;
                #pragma unroll
                for (int d = 0; d < 16; d++)
                    accv[r][d] += p * v[d];
            }
        }
        __syncthreads();
    }

    #pragma unroll
    for (int r = 0; r < 2; r++) {
        float inv = 1.f / lrun[r];
        int q = half_blk * 128 + qb + 64 * r;
        size_t ob = (size_t)(b * NTOK + q) * DIM + h * HD;
        #pragma unroll
        for (int k4 = 0; k4 < 4; k4++) {
            float y0 = accv[r][k4*4+0] * inv;
            float y1 = accv[r][k4*4+1] * inv;
            float y2 = accv[r][k4*4+2] * inv;
            float y3 = accv[r][k4*4+3] * inv;
            __half h0 = __float2half_rn(y0), h1 = __float2half_rn(y1);
            __half h2 = __float2half_rn(y2), h3 = __float2half_rn(y3);
            uint2 hi = make_uint2(pack_h2(y0, y1), pack_h2(y2, y3));
            uint2 lo = make_uint2(
                pack_h2(y0 - __half2float(h0), y1 - __half2float(h1)),
                pack_h2(y2 - __half2float(h2), y3 - __half2float(h3)));
            *(uint2*)(ohi + ob + k4 * 16 + g * 4) = hi;
            *(uint2*)(olo + ob + k4 * 16 + g * 4) = lo;
        }
    }
}

/* ------------------------------------------------------------------ */
/* Launch                                                              */
/* ------------------------------------------------------------------ */
extern "C" void kernel_launch(void* const* d_in, const int* in_sizes, int n_in,
                              void* d_out, int out_size) {
    const float* x      = (const float*)d_in[0];
    const float* pos    = (const float*)d_in[1];
    const float* rope   = (const float*)d_in[2];
    const float* ln1_w  = (const float*)d_in[3];
    const float* ln1_b  = (const float*)d_in[4];
    const float* wq     = (const float*)d_in[5];
    const float* bq     = (const float*)d_in[6];
    const float* wk     = (const float*)d_in[7];
    const float* wv     = (const float*)d_in[8];
    const float* bv     = (const float*)d_in[9];
    const float* wo     = (const float*)d_in[10];
    const float* bo     = (const float*)d_in[11];
    const float* ln2_w  = (const float*)d_in[12];
    const float* ln2_b  = (const float*)d_in[13];
    const float* w1g    = (const float*)d_in[14];
    const float* b1g    = (const float*)d_in[15];
    const float* w1x    = (const float*)d_in[16];
    const float* b1x    = (const float*)d_in[17];
    const float* lnm_w  = (const float*)d_in[18];
    const float* lnm_b  = (const float*)d_in[19];
    const float* w2     = (const float*)d_in[20];
    const float* b2     = (const float*)d_in[21];
    float* h = (float*)d_out;

    float *qkv, *gu, *bqkv, *b1, *part;
    __half *yhh, *yhl, *ohh, *ohl, *mhh, *mhl;
    __half *wqkvh, *wqkvl, *woh, *wol, *w1h, *w1l, *w2h, *w2l;
    cudaGetSymbolAddress((void**)&qkv,   g_qkv);
    cudaGetSymbolAddress((void**)&gu,    g_gu);
    cudaGetSymbolAddress((void**)&part,  g_part);
    cudaGetSymbolAddress((void**)&bqkv,  g_bqkv);
    cudaGetSymbolAddress((void**)&b1,    g_b1);
    cudaGetSymbolAddress((void**)&yhh,   g_yh_hi);
    cudaGetSymbolAddress((void**)&yhl,   g_yh_lo);
    cudaGetSymbolAddress((void**)&ohh,   g_oh_hi);
    cudaGetSymbolAddress((void**)&ohl,   g_oh_lo);
    cudaGetSymbolAddress((void**)&mhh,   g_mh_hi);
    cudaGetSymbolAddress((void**)&mhl,   g_mh_lo);
    cudaGetSymbolAddress((void**)&wqkvh, g_wqkv_hi);
    cudaGetSymbolAddress((void**)&wqkvl, g_wqkv_lo);
    cudaGetSymbolAddress((void**)&woh,   g_wo_hi);
    cudaGetSymbolAddress((void**)&wol,   g_wo_lo);
    cudaGetSymbolAddress((void**)&w1h,   g_w1_hi);
    cudaGetSymbolAddress((void**)&w1l,   g_w1_lo);
    cudaGetSymbolAddress((void**)&w2h,   g_w2_hi);
    cudaGetSymbolAddress((void**)&w2l,   g_w2_lo);

    cudaFuncSetAttribute((const void*)gemm_mma<true,false>,
                         cudaFuncAttributeMaxDynamicSharedMemorySize, GEMM_SMEM);
    cudaFuncSetAttribute((const void*)gemm_mma<false,false>,
                         cudaFuncAttributeMaxDynamicSharedMemorySize, GEMM_SMEM);
    cudaFuncSetAttribute((const void*)gemm_mma<false,true>,
                         cudaFuncAttributeMaxDynamicSharedMemorySize, GEMM_SMEM);
    cudaFuncSetAttribute((const void*)attn_kernel,
                         cudaFuncAttributeMaxDynamicSharedMemorySize, ATTN_SMEM);

    /* ---- [1] fused weight split + pack ---- */
    {
        const int nD = DIM*DIM, nH = HIDDEN*DIM;
        CvtArgs a;
        const float* srcs[7] = { wq, wk, wv, wo, w1g, w1x, w2 };
        __half* his[7] = { wqkvh, wqkvh, wqkvh, woh, w1h, w1h, w2h };
        __half* los[7] = { wqkvl, wqkvl, wqkvl, wol, w1l, w1l, w2l };
        int lrs[7]   = { nD, nD, nD, nD, nH, nH, nH };
        int ltots[7] = { QS*DIM, QS*DIM, QS*DIM, nD, GUS*DIM, GUS*DIM, nH };
        int offs[7]  = { 0, nD, 2*nD, 0, 0, nH, 0 };
        int cum = 0;
        for (int s = 0; s < 7; s++) {
            a.src[s] = srcs[s]; a.hi[s] = his[s]; a.lo[s] = los[s];
            a.lr[s] = lrs[s]; a.ltot[s] = ltots[s]; a.off[s] = offs[s];
            a.cum[s] = cum;
            cum += DEPTH * lrs[s] / 4;
        }
        a.cum[7] = cum;
        cvt_all<<<(cum + 255)/256, 256>>>(a, cum);
    }
    /* ---- [2] pos-embed add + bias packing ---- */
    add_pos_prep<<<(TOKENS*DIM + 255)/256, 256>>>(x, pos, h, bq, bv, bqkv,
                                                  b1g, b1x, b1);

    dim3 gQKV(QS/256,  TOKENS/128);      /* (9, 32)    */
    dim3 gMLP(GUS/256, TOKENS/128);      /* (16, 32)   */
    dim3 gSK (DIM/256, TOKENS/128, 3);   /* (3, 32, 3) */
    const int RED = (TOKENS*DIM/4 + 255)/256;

    for (int l = 0; l < DEPTH; l++) {
        size_t oqkv = (size_t)l * QS * DIM;
        size_t owo  = (size_t)l * DIM * DIM;
        size_t ow1  = (size_t)l * GUS * DIM;
        size_t ow2  = (size_t)l * DIM * HIDDEN;

        /* ---- attention (ln1 fused with previous layer's W2 reduce) ---- */
        ln_fused<<<TOKENS, 256>>>(h,
            l == 0 ? nullptr : part,
            l == 0 ? nullptr : b2 + (l-1)*DIM,
            ln1_w + l*DIM, ln1_b + l*DIM, yhh, yhl);
        gemm_mma<true,false><<<gQKV, 256, GEMM_SMEM>>>(
            yhh, yhl, wqkvh + oqkv, wqkvl + oqkv,
            bqkv + l*QS, nullptr, qkv, rope, TOKENS, QS, DIM);
        attn_kernel<<<BATCH*HEADS*2, 256, ATTN_SMEM>>>(qkv, ohh, ohl);
        gemm_mma<false,true><<<gSK, 256, GEMM_SMEM>>>(
            ohh, ohl, woh + owo, wol + owo,
            nullptr, nullptr, part, nullptr, TOKENS, DIM, DIM);

        /* ---- SwiGLU MLP (ln2 fused with O-proj reduce) ---- */
        ln_fused<<<TOKENS, 256>>>(h, part, bo + l*DIM,
            ln2_w + l*DIM, ln2_b + l*DIM, yhh, yhl);
        gemm_mma<false,false><<<gMLP, 256, GEMM_SMEM>>>(
            yhh, yhl, w1h + ow1, w1l + ow1,
            b1 + l*GUS, nullptr, gu, nullptr, TOKENS, GUS, DIM);
        mlp_act_ln_kernel<<<TOKENS, 256>>>(gu, lnm_w + l*HIDDEN, lnm_b + l*HIDDEN, mhh, mhl);
        gemm_mma<false,true><<<gSK, 256, GEMM_SMEM>>>(
            mhh, mhl, w2h + ow2, w2l + ow2,
            nullptr, nullptr, part, nullptr, TOKENS, DIM, HIDDEN);
    }
    /* final residual reduce */
    reduce3<<<RED, 256>>>(h, part, b2 + (DEPTH-1)*DIM);
}

// round 15
// speedup vs baseline: 2.4269x; 1.3144x over previous
#include <cuda_runtime.h>
#include <cuda_fp16.h>
#include <math.h>
#include <stdint.h>

#define DEPTH   12
#define BATCH   16
#define NTOK    256
#define TOKENS  (BATCH*NTOK)     /* 4096 */
#define DIM     768
#define HEADS   12
#define HD      64
#define HIDDEN  2048
#define EPSF    1e-5f
#define QS      2304             /* packed qkv row stride */
#define GUS     4096             /* packed g|u row stride */

/* ------------------------------------------------------------------ */
/* Scratch buffers                                                     */
/* ------------------------------------------------------------------ */
__device__ float  g_qkv[TOKENS*QS];
__device__ float  g_gu[TOKENS*GUS];
__device__ float  g_part[3*TOKENS*DIM];
__device__ __half g_yh_hi[TOKENS*DIM];
__device__ __half g_oh_hi[TOKENS*DIM];
__device__ __half g_mh_hi[TOKENS*HIDDEN];

/* packed split weights (B side keeps hi+lo) */
__device__ __half g_wqkv_hi[DEPTH*QS*DIM];
__device__ __half g_wqkv_lo[DEPTH*QS*DIM];
__device__ __half g_wo_hi[DEPTH*DIM*DIM];
__device__ __half g_wo_lo[DEPTH*DIM*DIM];
__device__ __half g_w1_hi[DEPTH*GUS*DIM];
__device__ __half g_w1_lo[DEPTH*GUS*DIM];
__device__ __half g_w2_hi[DEPTH*DIM*HIDDEN];
__device__ __half g_w2_lo[DEPTH*DIM*HIDDEN];
__device__ float  g_bqkv[DEPTH*QS];
__device__ float  g_b1[DEPTH*GUS];

/* ------------------------------------------------------------------ */
/* PTX helpers                                                         */
/* ------------------------------------------------------------------ */
__device__ __forceinline__ uint32_t smem_u32(const void* p) {
    uint32_t a;
    asm("{ .reg .u64 t; cvta.to.shared.u64 t, %1; cvt.u32.u64 %0, t; }"
        : "=r"(a) : "l"(p));
    return a;
}
__device__ __forceinline__ void cp16(uint32_t dst, const void* src) {
    asm volatile("cp.async.cg.shared.global [%0], [%1], 16;"
                 :: "r"(dst), "l"(src) : "memory");
}
__device__ __forceinline__ void cp_commit() {
    asm volatile("cp.async.commit_group;" ::: "memory");
}
template<int NWAIT>
__device__ __forceinline__ void cp_wait() {
    asm volatile("cp.async.wait_group %0;" :: "n"(NWAIT) : "memory");
}
template<int IMM>
__device__ __forceinline__ void ldmx4i(uint32_t& r0, uint32_t& r1,
                                       uint32_t& r2, uint32_t& r3, uint32_t a) {
    asm volatile("ldmatrix.sync.aligned.m8n8.x4.shared.b16 {%0,%1,%2,%3}, [%4+%5];"
                 : "=r"(r0), "=r"(r1), "=r"(r2), "=r"(r3) : "r"(a), "n"(IMM));
}
#define LDM4(f, base) do {                                        \
    ldmx4i<0>   ((f)[0][0], (f)[0][1], (f)[0][2], (f)[0][3], base); \
    ldmx4i<2048>((f)[1][0], (f)[1][1], (f)[1][2], (f)[1][3], base); \
    ldmx4i<4096>((f)[2][0], (f)[2][1], (f)[2][2], (f)[2][3], base); \
    ldmx4i<6144>((f)[3][0], (f)[3][1], (f)[3][2], (f)[3][3], base); \
} while (0)

__device__ __forceinline__ void mma16816(float* c, const uint32_t* a,
                                         uint32_t b0, uint32_t b1) {
    asm("mma.sync.aligned.m16n8k16.row.col.f32.f16.f16.f32 "
        "{%0,%1,%2,%3}, {%4,%5,%6,%7}, {%8,%9}, {%0,%1,%2,%3};"
        : "+f"(c[0]), "+f"(c[1]), "+f"(c[2]), "+f"(c[3])
        : "r"(a[0]), "r"(a[1]), "r"(a[2]), "r"(a[3]), "r"(b0), "r"(b1));
}

/* ------------------------------------------------------------------ */
/* 2-term split GEMM (NT): C = Ah*(Bhi + Blo)  (+bias)(+res)(+rope)    */
/* CTA tile 128x256, 8 warps of 64x64 (2x4), BK=64, double-buffered.   */
/* A single fp16 plane; B split hi/lo (weights exactly corrected).     */
/* ------------------------------------------------------------------ */
#define PA 16384
#define PB 32768
#define BUFSZ (PA + 2*PB)              /* 81920 */
#define GEMM_SMEM (2*BUFSZ)            /* 163840 */

template<bool ROPE, bool PARTIAL>
__global__ void __launch_bounds__(256, 1) gemm_mma(
    const __half* __restrict__ Ah,
    const __half* __restrict__ Bhi, const __half* __restrict__ Blo,
    const float* __restrict__ bias, const float* __restrict__ res,
    float* __restrict__ C, const float* __restrict__ remb,
    int M, int N, int K) {
    extern __shared__ __align__(128) char smem[];
    uint32_t sb = smem_u32(smem);
    int tid = threadIdx.x, wid = tid >> 5, lane = tid & 31;
    int wm = wid >> 2, wn = wid & 3;
    int bm = blockIdx.y * 128, bn = blockIdx.x * 256;

    int l15 = lane & 15, kg = lane >> 4;
    uint32_t arow = (uint32_t)(wm * 64 + l15);
    uint32_t brow = (uint32_t)(wn * 64 + l15);
    int aswz = (int)(arow & 7), bswz = (int)(brow & 7);

    uint32_t aoff[4], boff[4];
    #pragma unroll
    for (int ks = 0; ks < 4; ks++) {
        int g = ks * 2 + kg;
        aoff[ks] = (uint32_t)((g ^ aswz) * 16);
        boff[ks] = (uint32_t)((g ^ bswz) * 16);
    }
    uint32_t aB0  = sb           + arow * 128u;
    uint32_t bHi0 = sb + PA      + brow * 128u;
    uint32_t bLo0 = sb + PA + PB + brow * 128u;

    float acc[4][8][4];
    #pragma unroll
    for (int i = 0; i < 4; i++)
        #pragma unroll
        for (int j = 0; j < 8; j++)
            #pragma unroll
            for (int e = 0; e < 4; e++) acc[i][j][e] = 0.f;

    int nch = K >> 6;
    int c0 = 0, c1 = nch;
    if (PARTIAL) {
        int z = blockIdx.z;
        c0 = (z * nch) / 3;
        c1 = ((z + 1) * nch) / 3;
    }

    auto load_chunk = [&](uint32_t dst, int ko) {
        #pragma unroll
        for (int j = 0; j < 4; j++) {
            int id = tid + j * 256;
            int row = id >> 3, g = id & 7;
            uint32_t off = (uint32_t)row * 128u + (uint32_t)((g ^ (row & 7)) * 16);
            size_t so = (size_t)(bm + row) * K + ko + g * 8;
            cp16(dst + off, Ah + so);
        }
        #pragma unroll
        for (int j = 0; j < 8; j++) {
            int id = tid + j * 256;
            int row = id >> 3, g = id & 7;
            uint32_t off = (uint32_t)row * 128u + (uint32_t)((g ^ (row & 7)) * 16);
            size_t so = (size_t)(bn + row) * K + ko + g * 8;
            cp16(dst + PA + off,      Bhi + so);
            cp16(dst + PA + PB + off, Blo + so);
        }
    };

    load_chunk(sb, c0 * 64);
    cp_commit();

    for (int c = c0; c < c1; c++) {
        if (c + 1 < c1) {
            load_chunk(sb + (uint32_t)(((c - c0 + 1) & 1) * BUFSZ), (c + 1) * 64);
            cp_commit();
            cp_wait<1>();
        } else {
            cp_wait<0>();
        }
        __syncthreads();

        uint32_t bofs = (uint32_t)(((c - c0) & 1) ? BUFSZ : 0);
        uint32_t a_b  = aB0  + bofs;
        uint32_t b_hi = bHi0 + bofs;
        uint32_t b_lo = bLo0 + bofs;

        #pragma unroll
        for (int ks = 0; ks < 4; ks++) {
            uint32_t afh[4][4], bfh[4][4];
            LDM4(afh, a_b  + aoff[ks]);
            LDM4(bfh, b_hi + boff[ks]);
            #pragma unroll
            for (int mf = 0; mf < 4; mf++)
                #pragma unroll
                for (int nf = 0; nf < 8; nf++)
                    mma16816(acc[mf][nf], afh[mf],
                             bfh[nf >> 1][nf & 1], bfh[nf >> 1][(nf & 1) + 2]);
            {
                uint32_t bfl[4][4];
                LDM4(bfl, b_lo + boff[ks]);
                #pragma unroll
                for (int mf = 0; mf < 4; mf++)
                    #pragma unroll
                    for (int nf = 0; nf < 8; nf++)
                        mma16816(acc[mf][nf], afh[mf],
                                 bfl[nf >> 1][nf & 1], bfl[nf >> 1][(nf & 1) + 2]);
            }
        }
        __syncthreads();
    }

    int r0 = lane >> 2, cb = (lane & 3) * 2;
    if (PARTIAL) {
        float* Cp = C + (size_t)blockIdx.z * M * N;
        #pragma unroll
        for (int mf = 0; mf < 4; mf++)
            #pragma unroll
            for (int nf = 0; nf < 8; nf++) {
                int n0 = bn + wn * 64 + nf * 8 + cb;
                #pragma unroll
                for (int half = 0; half < 2; half++) {
                    int m0 = bm + wm * 64 + mf * 16 + r0 + half * 8;
                    *(float2*)(Cp + (size_t)m0 * N + n0) =
                        make_float2(acc[mf][nf][half * 2], acc[mf][nf][half * 2 + 1]);
                }
            }
        return;
    }
    #pragma unroll
    for (int mf = 0; mf < 4; mf++) {
        #pragma unroll
        for (int nf = 0; nf < 8; nf++) {
            int n0 = bn + wn * 64 + nf * 8 + cb;
            float bz0 = bias ? bias[n0]     : 0.f;
            float bz1 = bias ? bias[n0 + 1] : 0.f;
            #pragma unroll
            for (int half = 0; half < 2; half++) {
                int m0 = bm + wm * 64 + mf * 16 + r0 + half * 8;
                float v0 = acc[mf][nf][half * 2]     + bz0;
                float v1 = acc[mf][nf][half * 2 + 1] + bz1;
                if (ROPE) {
                    if (n0 < 2*DIM) {
                        int pos = m0 & (NTOK - 1);
                        int d   = n0 & (HD - 1);
                        const float* e = remb + pos * (2*HD);
                        float2 sn = *(const float2*)(e + d);
                        float2 cs = *(const float2*)(e + HD + d);
                        float t0 = v0 * cs.x - v1 * sn.x;
                        float t1 = v1 * cs.y + v0 * sn.y;
                        v0 = t0; v1 = t1;
                    }
                }
                size_t idx = (size_t)m0 * N + n0;
                if (res) { v0 += res[idx]; v1 += res[idx + 1]; }
                *(float2*)(C + idx) = make_float2(v0, v1);
            }
        }
    }
}

/* ------------------------------------------------------------------ */
/* reduce3: h += bias + p0 + p1 + p2 (final layer only)                */
/* ------------------------------------------------------------------ */
__global__ void reduce3(float* __restrict__ h, const float* __restrict__ part,
                        const float* __restrict__ bias) {
    int i = blockIdx.x * blockDim.x + threadIdx.x;
    if (i >= TOKENS*DIM/4) return;
    float4 a  = ((const float4*)h)[i];
    float4 p0 = ((const float4*)part)[i];
    float4 p1 = ((const float4*)(part + TOKENS*DIM))[i];
    float4 p2 = ((const float4*)(part + 2*TOKENS*DIM))[i];
    float4 bz = *(const float4*)(bias + (i*4) % DIM);
    a.x += bz.x + ((p0.x + p1.x) + p2.x);
    a.y += bz.y + ((p0.y + p1.y) + p2.y);
    a.z += bz.z + ((p0.z + p1.z) + p2.z);
    a.w += bz.w + ((p0.w + p1.w) + p2.w);
    ((float4*)h)[i] = a;
}

/* ------------------------------------------------------------------ */
/* Single fused fp32 -> (hi, lo) split+pack for ALL weights            */
/* ------------------------------------------------------------------ */
struct CvtArgs {
    const float* src[7];
    __half* hi[7];
    __half* lo[7];
    int lr[7];
    int ltot[7];
    int off[7];
    int cum[8];
};
__device__ __forceinline__ void split2(float a, float b, __half2& h, __half2& l) {
    __half ha = __float2half_rn(a), hb = __float2half_rn(b);
    __half la = __float2half_rn(a - __half2float(ha));
    __half lb = __float2half_rn(b - __half2float(hb));
    h = __halves2half2(ha, hb);
    l = __halves2half2(la, lb);
}
__global__ void cvt_all(CvtArgs a, int total4) {
    int i4 = blockIdx.x * blockDim.x + threadIdx.x;
    if (i4 >= total4) return;
    int s = 0;
    #pragma unroll
    for (int j = 1; j < 7; j++) s += (i4 >= a.cum[j]);
    int i = (i4 - a.cum[s]) * 4;
    int l = i / a.lr[s];
    int rem = i - l * a.lr[s];
    size_t d = (size_t)l * a.ltot[s] + a.off[s] + rem;
    float4 v = *(const float4*)(a.src[s] + i);
    __half2 h0, l0, h1, l1;
    split2(v.x, v.y, h0, l0);
    split2(v.z, v.w, h1, l1);
    ((__half2*)(a.hi[s] + d))[0] = h0; ((__half2*)(a.hi[s] + d))[1] = h1;
    ((__half2*)(a.lo[s] + d))[0] = l0; ((__half2*)(a.lo[s] + d))[1] = l1;
}

/* ------------------------------------------------------------------ */
/* add_pos + bias packing fused                                        */
/* ------------------------------------------------------------------ */
__global__ void add_pos_prep(const float* __restrict__ x,
                             const float* __restrict__ pos,
                             float* __restrict__ h,
                             const float* __restrict__ bq,
                             const float* __restrict__ bv,
                             float* __restrict__ bqkv,
                             const float* __restrict__ bg,
                             const float* __restrict__ bx,
                             float* __restrict__ b1) {
    int idx = blockIdx.x * blockDim.x + threadIdx.x;
    if (idx < TOKENS*DIM) h[idx] = x[idx] + pos[idx % (NTOK*DIM)];
    if (idx < DEPTH*QS) {
        int l = idx / QS, c = idx % QS;
        bqkv[idx] = c < DIM ? bq[l*DIM + c]
                  : (c < 2*DIM ? 0.f : bv[l*DIM + c - 2*DIM]);
    }
    if (idx < DEPTH*GUS) {
        int l = idx / GUS, c = idx % GUS;
        b1[idx] = c < HIDDEN ? bg[l*HIDDEN + c] : bx[l*HIDDEN + c - HIDDEN];
    }
}

/* ------------------------------------------------------------------ */
/* Block reductions (256 threads)                                      */
/* ------------------------------------------------------------------ */
__device__ __forceinline__ float2 block_reduce_2(float s, float s2) {
    __shared__ float red[16];
    #pragma unroll
    for (int o = 16; o > 0; o >>= 1) {
        s  += __shfl_down_sync(0xffffffffu, s,  o);
        s2 += __shfl_down_sync(0xffffffffu, s2, o);
    }
    int w = threadIdx.x >> 5, l = threadIdx.x & 31;
    if (l == 0) { red[w] = s; red[8 + w] = s2; }
    __syncthreads();
    if (threadIdx.x < 32) {
        s  = (l < 8) ? red[l]     : 0.f;
        s2 = (l < 8) ? red[8 + l] : 0.f;
        #pragma unroll
        for (int o = 4; o > 0; o >>= 1) {
            s  += __shfl_down_sync(0xffffffffu, s,  o);
            s2 += __shfl_down_sync(0xffffffffu, s2, o);
        }
        if (l == 0) { red[0] = s; red[1] = s2; }
    }
    __syncthreads();
    return make_float2(red[0], red[1]);
}
__device__ __forceinline__ float block_reduce_max(float m) {
    __shared__ float redm[8];
    #pragma unroll
    for (int o = 16; o > 0; o >>= 1)
        m = fmaxf(m, __shfl_xor_sync(0xffffffffu, m, o));
    int w = threadIdx.x >> 5, l = threadIdx.x & 31;
    if (l == 0) redm[w] = m;
    __syncthreads();
    if (threadIdx.x < 32) {
        m = (l < 8) ? redm[l] : 0.f;
        #pragma unroll
        for (int o = 4; o > 0; o >>= 1)
            m = fmaxf(m, __shfl_xor_sync(0xffffffffu, m, o));
        if (l == 0) redm[0] = m;
    }
    __syncthreads();
    return redm[0];
}

__device__ __forceinline__ uint32_t pack_h2(float a, float b) {
    __half2 h = __floats2half2_rn(a, b);
    return *(uint32_t*)&h;
}

/* ------------------------------------------------------------------ */
/* Fused residual-reduce + LayerNorm over DIM (hi-plane output only)   */
/* ------------------------------------------------------------------ */
__global__ void __launch_bounds__(256) ln_fused(
    float* __restrict__ h, const float* __restrict__ part,
    const float* __restrict__ gbias,
    const float* __restrict__ w, const float* __restrict__ b,
    __half* __restrict__ ohi) {
    int t = blockIdx.x;
    int c4 = threadIdx.x;
    size_t i4 = (size_t)t * (DIM/4) + c4;
    float4 v = make_float4(0.f, 0.f, 0.f, 0.f);
    if (c4 < DIM/4) {
        v = ((const float4*)h)[i4];
        if (part) {
            float4 p0 = ((const float4*)part)[i4];
            float4 p1 = ((const float4*)(part + TOKENS*DIM))[i4];
            float4 p2 = ((const float4*)(part + 2*TOKENS*DIM))[i4];
            float4 bz = ((const float4*)gbias)[c4];
            v.x += bz.x + ((p0.x + p1.x) + p2.x);
            v.y += bz.y + ((p0.y + p1.y) + p2.y);
            v.z += bz.z + ((p0.z + p1.z) + p2.z);
            v.w += bz.w + ((p0.w + p1.w) + p2.w);
            ((float4*)h)[i4] = v;
        }
    }
    float s  = v.x + v.y + v.z + v.w;
    float s2 = v.x*v.x + v.y*v.y + v.z*v.z + v.w*v.w;
    float2 r = block_reduce_2(s, s2);
    float mean = r.x / DIM;
    float var  = r.y / DIM - mean * mean;
    float inv  = rsqrtf(var + EPSF);
    if (c4 < DIM/4) {
        float4 wv = ((const float4*)w)[c4];
        float4 bv = ((const float4*)b)[c4];
        float y0 = (v.x - mean) * inv * wv.x + bv.x;
        float y1 = (v.y - mean) * inv * wv.y + bv.y;
        float y2 = (v.z - mean) * inv * wv.z + bv.z;
        float y3 = (v.w - mean) * inv * wv.w + bv.w;
        ((uint2*)ohi)[i4] = make_uint2(pack_h2(y0, y1), pack_h2(y2, y3));
    }
}

/* ------------------------------------------------------------------ */
/* silu(g)*u then LN over HIDDEN (hi-plane output only)                */
/* ------------------------------------------------------------------ */
__global__ void __launch_bounds__(256) mlp_act_ln_kernel(
    const float* __restrict__ gu,
    const float* __restrict__ w, const float* __restrict__ b,
    __half* __restrict__ ohi) {
    int t = blockIdx.x;
    const float* gr = gu + (size_t)t * GUS;
    const float* ur = gr + HIDDEN;
    float a[8];
    float s = 0.f, s2 = 0.f;
    #pragma unroll
    for (int j = 0; j < 2; j++) {
        int c4 = threadIdx.x + j * 256;
        float4 gv = ((const float4*)gr)[c4];
        float4 uv = ((const float4*)ur)[c4];
        float* aj = a + j * 4;
        aj[0] = gv.x / (1.f + __expf(-gv.x)) * uv.x;
        aj[1] = gv.y / (1.f + __expf(-gv.y)) * uv.y;
        aj[2] = gv.z / (1.f + __expf(-gv.z)) * uv.z;
        aj[3] = gv.w / (1.f + __expf(-gv.w)) * uv.w;
        s  += aj[0] + aj[1] + aj[2] + aj[3];
        s2 += aj[0]*aj[0] + aj[1]*aj[1] + aj[2]*aj[2] + aj[3]*aj[3];
    }
    float2 r = block_reduce_2(s, s2);
    float mean = r.x / HIDDEN;
    float var  = r.y / HIDDEN - mean * mean;
    float inv  = rsqrtf(var + EPSF);
    #pragma unroll
    for (int j = 0; j < 2; j++) {
        int c4 = threadIdx.x + j * 256;
        float4 wv = ((const float4*)w)[c4];
        float4 bv = ((const float4*)b)[c4];
        float* aj = a + j * 4;
        float y0 = (aj[0] - mean) * inv * wv.x + bv.x;
        float y1 = (aj[1] - mean) * inv * wv.y + bv.y;
        float y2 = (aj[2] - mean) * inv * wv.z + bv.z;
        float y3 = (aj[3] - mean) * inv * wv.w + bv.w;
        ((uint2*)ohi)[(size_t)t * (HIDDEN/4) + c4] =
            make_uint2(pack_h2(y0, y1), pack_h2(y2, y3));
    }
}

/* ------------------------------------------------------------------ */
/* Attention: 2 queries/thread, quad-strided slices, static max bound  */
/* ------------------------------------------------------------------ */
#define KVT 128
#define ATTN_SMEM (2*KVT*HD*4)    /* 65536 */
__global__ void __launch_bounds__(256) attn_kernel(
    const float* __restrict__ qkv, __half* __restrict__ ohi) {
    extern __shared__ float sm[];
    float* Ks = sm;
    float* Vs = sm + KVT * HD;
    int blk = blockIdx.x;
    int half_blk = blk & 1;
    int bh = blk >> 1;
    int b  = bh / HEADS, h = bh % HEADS;
    size_t base = (size_t)(b * NTOK) * QS + h * HD;
    int tid = threadIdx.x;
    int g  = tid & 3;
    int qb = tid >> 2;
    const float scale = 0.125f;

    float km2 = 0.f;
    {
        const float* kp = qkv + base + (size_t)tid * QS + DIM;
        #pragma unroll 4
        for (int c4 = 0; c4 < 16; c4++) {
            float4 t = *(const float4*)(kp + c4 * 4);
            km2 += t.x*t.x + t.y*t.y + t.z*t.z + t.w*t.w;
        }
    }
    float kmax = sqrtf(block_reduce_max(km2));

    float qreg[2][16], accv[2][16], lrun[2], Mq[2];
    #pragma unroll
    for (int r = 0; r < 2; r++) {
        int q = half_blk * 128 + qb + 64 * r;
        const float* qp = qkv + base + (size_t)q * QS;
        float qn2 = 0.f;
        #pragma unroll
        for (int k4 = 0; k4 < 4; k4++) {
            float4 v = *(const float4*)(qp + k4 * 16 + g * 4);
            qreg[r][k4*4+0] = v.x * scale;
            qreg[r][k4*4+1] = v.y * scale;
            qreg[r][k4*4+2] = v.z * scale;
            qreg[r][k4*4+3] = v.w * scale;
            qn2 += qreg[r][k4*4+0]*qreg[r][k4*4+0] + qreg[r][k4*4+1]*qreg[r][k4*4+1]
                 + qreg[r][k4*4+2]*qreg[r][k4*4+2] + qreg[r][k4*4+3]*qreg[r][k4*4+3];
        }
        qn2 += __shfl_xor_sync(0xffffffffu, qn2, 1);
        qn2 += __shfl_xor_sync(0xffffffffu, qn2, 2);
        Mq[r] = sqrtf(qn2) * kmax;
        lrun[r] = 0.f;
        #pragma unroll
        for (int d = 0; d < 16; d++) accv[r][d] = 0.f;
    }

    for (int tkv = 0; tkv < NTOK / KVT; tkv++) {
        for (int i4 = tid; i4 < KVT * HD / 4; i4 += 256) {
            int row = i4 >> 4, c4 = i4 & 15;
            size_t src = base + (size_t)(tkv * KVT + row) * QS;
            ((float4*)Ks)[i4] = *(const float4*)(qkv + src + DIM   + c4 * 4);
            ((float4*)Vs)[i4] = *(const float4*)(qkv + src + 2*DIM + c4 * 4);
        }
        __syncthreads();

        for (int j = 0; j < KVT; j++) {
            float k[16], v[16];
            const float* kr = Ks + j * HD;
            const float* vr = Vs + j * HD;
            #pragma unroll
            for (int k4 = 0; k4 < 4; k4++) {
                float4 t = *(const float4*)(kr + k4 * 16 + g * 4);
                k[k4*4+0]=t.x; k[k4*4+1]=t.y; k[k4*4+2]=t.z; k[k4*4+3]=t.w;
                float4 u = *(const float4*)(vr + k4 * 16 + g * 4);
                v[k4*4+0]=u.x; v[k4*4+1]=u.y; v[k4*4+2]=u.z; v[k4*4+3]=u.w;
            }
            #pragma unroll
            for (int r = 0; r < 2; r++) {
                float s = 0.f;
                #pragma unroll
                for (int d = 0; d < 16; d++) s += qreg[r][d] * k[d];
                s += __shfl_xor_sync(0xffffffffu, s, 1);
                s += __shfl_xor_sync(0xffffffffu, s, 2);
                float p = __expf(s - Mq[r]);
                lrun[r] += p;
                #pragma unroll
                for (int d = 0; d < 16; d++)
                    accv[r][d] += p * v[d];
            }
        }
        __syncthreads();
    }

    #pragma unroll
    for (int r = 0; r < 2; r++) {
        float inv = 1.f / lrun[r];
        int q = half_blk * 128 + qb + 64 * r;
        size_t ob = (size_t)(b * NTOK + q) * DIM + h * HD;
        #pragma unroll
        for (int k4 = 0; k4 < 4; k4++) {
            float y0 = accv[r][k4*4+0] * inv;
            float y1 = accv[r][k4*4+1] * inv;
            float y2 = accv[r][k4*4+2] * inv;
            float y3 = accv[r][k4*4+3] * inv;
            *(uint2*)(ohi + ob + k4 * 16 + g * 4) =
                make_uint2(pack_h2(y0, y1), pack_h2(y2, y3));
        }
    }
}

/* ------------------------------------------------------------------ */
/* Launch                                                              */
/* ------------------------------------------------------------------ */
extern "C" void kernel_launch(void* const* d_in, const int* in_sizes, int n_in,
                              void* d_out, int out_size) {
    const float* x      = (const float*)d_in[0];
    const float* pos    = (const float*)d_in[1];
    const float* rope   = (const float*)d_in[2];
    const float* ln1_w  = (const float*)d_in[3];
    const float* ln1_b  = (const float*)d_in[4];
    const float* wq     = (const float*)d_in[5];
    const float* bq     = (const float*)d_in[6];
    const float* wk     = (const float*)d_in[7];
    const float* wv     = (const float*)d_in[8];
    const float* bv     = (const float*)d_in[9];
    const float* wo     = (const float*)d_in[10];
    const float* bo     = (const float*)d_in[11];
    const float* ln2_w  = (const float*)d_in[12];
    const float* ln2_b  = (const float*)d_in[13];
    const float* w1g    = (const float*)d_in[14];
    const float* b1g    = (const float*)d_in[15];
    const float* w1x    = (const float*)d_in[16];
    const float* b1x    = (const float*)d_in[17];
    const float* lnm_w  = (const float*)d_in[18];
    const float* lnm_b  = (const float*)d_in[19];
    const float* w2     = (const float*)d_in[20];
    const float* b2     = (const float*)d_in[21];
    float* h = (float*)d_out;

    float *qkv, *gu, *bqkv, *b1, *part;
    __half *yhh, *ohh, *mhh;
    __half *wqkvh, *wqkvl, *woh, *wol, *w1h, *w1l, *w2h, *w2l;
    cudaGetSymbolAddress((void**)&qkv,   g_qkv);
    cudaGetSymbolAddress((void**)&gu,    g_gu);
    cudaGetSymbolAddress((void**)&part,  g_part);
    cudaGetSymbolAddress((void**)&bqkv,  g_bqkv);
    cudaGetSymbolAddress((void**)&b1,    g_b1);
    cudaGetSymbolAddress((void**)&yhh,   g_yh_hi);
    cudaGetSymbolAddress((void**)&ohh,   g_oh_hi);
    cudaGetSymbolAddress((void**)&mhh,   g_mh_hi);
    cudaGetSymbolAddress((void**)&wqkvh, g_wqkv_hi);
    cudaGetSymbolAddress((void**)&wqkvl, g_wqkv_lo);
    cudaGetSymbolAddress((void**)&woh,   g_wo_hi);
    cudaGetSymbolAddress((void**)&wol,   g_wo_lo);
    cudaGetSymbolAddress((void**)&w1h,   g_w1_hi);
    cudaGetSymbolAddress((void**)&w1l,   g_w1_lo);
    cudaGetSymbolAddress((void**)&w2h,   g_w2_hi);
    cudaGetSymbolAddress((void**)&w2l,   g_w2_lo);

    cudaFuncSetAttribute((const void*)gemm_mma<true,false>,
                         cudaFuncAttributeMaxDynamicSharedMemorySize, GEMM_SMEM);
    cudaFuncSetAttribute((const void*)gemm_mma<false,false>,
                         cudaFuncAttributeMaxDynamicSharedMemorySize, GEMM_SMEM);
    cudaFuncSetAttribute((const void*)gemm_mma<false,true>,
                         cudaFuncAttributeMaxDynamicSharedMemorySize, GEMM_SMEM);
    cudaFuncSetAttribute((const void*)attn_kernel,
                         cudaFuncAttributeMaxDynamicSharedMemorySize, ATTN_SMEM);

    /* ---- [1] fused weight split + pack ---- */
    {
        const int nD = DIM*DIM, nH = HIDDEN*DIM;
        CvtArgs a;
        const float* srcs[7] = { wq, wk, wv, wo, w1g, w1x, w2 };
        __half* his[7] = { wqkvh, wqkvh, wqkvh, woh, w1h, w1h, w2h };
        __half* los[7] = { wqkvl, wqkvl, wqkvl, wol, w1l, w1l, w2l };
        int lrs[7]   = { nD, nD, nD, nD, nH, nH, nH };
        int ltots[7] = { QS*DIM, QS*DIM, QS*DIM, nD, GUS*DIM, GUS*DIM, nH };
        int offs[7]  = { 0, nD, 2*nD, 0, 0, nH, 0 };
        int cum = 0;
        for (int s = 0; s < 7; s++) {
            a.src[s] = srcs[s]; a.hi[s] = his[s]; a.lo[s] = los[s];
            a.lr[s] = lrs[s]; a.ltot[s] = ltots[s]; a.off[s] = offs[s];
            a.cum[s] = cum;
            cum += DEPTH * lrs[s] / 4;
        }
        a.cum[7] = cum;
        cvt_all<<<(cum + 255)/256, 256>>>(a, cum);
    }
    /* ---- [2] pos-embed add + bias packing ---- */
    add_pos_prep<<<(TOKENS*DIM + 255)/256, 256>>>(x, pos, h, bq, bv, bqkv,
                                                  b1g, b1x, b1);

    dim3 gQKV(QS/256,  TOKENS/128);      /* (9, 32)    */
    dim3 gMLP(GUS/256, TOKENS/128);      /* (16, 32)   */
    dim3 gSK (DIM/256, TOKENS/128, 3);   /* (3, 32, 3) */
    const int RED = (TOKENS*DIM/4 + 255)/256;

    for (int l = 0; l < DEPTH; l++) {
        size_t oqkv = (size_t)l * QS * DIM;
        size_t owo  = (size_t)l * DIM * DIM;
        size_t ow1  = (size_t)l * GUS * DIM;
        size_t ow2  = (size_t)l * DIM * HIDDEN;

        /* ---- attention (ln1 fused with previous layer's W2 reduce) ---- */
        ln_fused<<<TOKENS, 256>>>(h,
            l == 0 ? nullptr : part,
            l == 0 ? nullptr : b2 + (l-1)*DIM,
            ln1_w + l*DIM, ln1_b + l*DIM, yhh);
        gemm_mma<true,false><<<gQKV, 256, GEMM_SMEM>>>(
            yhh, wqkvh + oqkv, wqkvl + oqkv,
            bqkv + l*QS, nullptr, qkv, rope, TOKENS, QS, DIM);
        attn_kernel<<<BATCH*HEADS*2, 256, ATTN_SMEM>>>(qkv, ohh);
        gemm_mma<false,true><<<gSK, 256, GEMM_SMEM>>>(
            ohh, woh + owo, wol + owo,
            nullptr, nullptr, part, nullptr, TOKENS, DIM, DIM);

        /* ---- SwiGLU MLP (ln2 fused with O-proj reduce) ---- */
        ln_fused<<<TOKENS, 256>>>(h, part, bo + l*DIM,
            ln2_w + l*DIM, ln2_b + l*DIM, yhh);
        gemm_mma<false,false><<<gMLP, 256, GEMM_SMEM>>>(
            yhh, w1h + ow1, w1l + ow1,
            b1 + l*GUS, nullptr, gu, nullptr, TOKENS, GUS, DIM);
        mlp_act_ln_kernel<<<TOKENS, 256>>>(gu, lnm_w + l*HIDDEN, lnm_b + l*HIDDEN, mhh);
        gemm_mma<false,true><<<gSK, 256, GEMM_SMEM>>>(
            mhh, w2h + ow2, w2l + ow2,
            nullptr, nullptr, part, nullptr, TOKENS, DIM, HIDDEN);
    }
    /* final residual reduce */
    reduce3<<<RED, 256>>>(h, part, b2 + (DEPTH-1)*DIM);
}

// round 16
// speedup vs baseline: 2.4759x; 1.0202x over previous
#include <cuda_runtime.h>
#include <cuda_fp16.h>
#include <math.h>
#include <stdint.h>

#define DEPTH   12
#define BATCH   16
#define NTOK    256
#define TOKENS  (BATCH*NTOK)     /* 4096 */
#define DIM     768
#define HEADS   12
#define HD      64
#define HIDDEN  2048
#define EPSF    1e-5f
#define QS      2304             /* packed qkv row stride */
#define GUS     4096             /* packed g|u row stride */

/* ------------------------------------------------------------------ */
/* Scratch buffers                                                     */
/* ------------------------------------------------------------------ */
__device__ float  g_qkv[TOKENS*QS];
__device__ float  g_gu[TOKENS*GUS];
__device__ float  g_part[3*TOKENS*DIM];
__device__ __half g_yh_hi[TOKENS*DIM];
__device__ __half g_oh_hi[TOKENS*DIM];
__device__ __half g_mh_hi[TOKENS*HIDDEN];

/* packed split weights (B side keeps hi+lo) */
__device__ __half g_wqkv_hi[DEPTH*QS*DIM];
__device__ __half g_wqkv_lo[DEPTH*QS*DIM];
__device__ __half g_wo_hi[DEPTH*DIM*DIM];
__device__ __half g_wo_lo[DEPTH*DIM*DIM];
__device__ __half g_w1_hi[DEPTH*GUS*DIM];
__device__ __half g_w1_lo[DEPTH*GUS*DIM];
__device__ __half g_w2_hi[DEPTH*DIM*HIDDEN];
__device__ __half g_w2_lo[DEPTH*DIM*HIDDEN];
__device__ float  g_bqkv[DEPTH*QS];
__device__ float  g_b1[DEPTH*GUS];

/* ------------------------------------------------------------------ */
/* PTX helpers                                                         */
/* ------------------------------------------------------------------ */
__device__ __forceinline__ uint32_t smem_u32(const void* p) {
    uint32_t a;
    asm("{ .reg .u64 t; cvta.to.shared.u64 t, %1; cvt.u32.u64 %0, t; }"
        : "=r"(a) : "l"(p));
    return a;
}
__device__ __forceinline__ void cp16(uint32_t dst, const void* src) {
    asm volatile("cp.async.cg.shared.global [%0], [%1], 16;"
                 :: "r"(dst), "l"(src) : "memory");
}
__device__ __forceinline__ void cp_commit() {
    asm volatile("cp.async.commit_group;" ::: "memory");
}
template<int NWAIT>
__device__ __forceinline__ void cp_wait() {
    asm volatile("cp.async.wait_group %0;" :: "n"(NWAIT) : "memory");
}
template<int IMM>
__device__ __forceinline__ void ldmx4i(uint32_t& r0, uint32_t& r1,
                                       uint32_t& r2, uint32_t& r3, uint32_t a) {
    asm volatile("ldmatrix.sync.aligned.m8n8.x4.shared.b16 {%0,%1,%2,%3}, [%4+%5];"
                 : "=r"(r0), "=r"(r1), "=r"(r2), "=r"(r3) : "r"(a), "n"(IMM));
}
#define LDM4(f, base) do {                                        \
    ldmx4i<0>   ((f)[0][0], (f)[0][1], (f)[0][2], (f)[0][3], base); \
    ldmx4i<2048>((f)[1][0], (f)[1][1], (f)[1][2], (f)[1][3], base); \
    ldmx4i<4096>((f)[2][0], (f)[2][1], (f)[2][2], (f)[2][3], base); \
    ldmx4i<6144>((f)[3][0], (f)[3][1], (f)[3][2], (f)[3][3], base); \
} while (0)

__device__ __forceinline__ void mma16816(float* c, const uint32_t* a,
                                         uint32_t b0, uint32_t b1) {
    asm("mma.sync.aligned.m16n8k16.row.col.f32.f16.f16.f32 "
        "{%0,%1,%2,%3}, {%4,%5,%6,%7}, {%8,%9}, {%0,%1,%2,%3};"
        : "+f"(c[0]), "+f"(c[1]), "+f"(c[2]), "+f"(c[3])
        : "r"(a[0]), "r"(a[1]), "r"(a[2]), "r"(a[3]), "r"(b0), "r"(b1));
}
/* packed f32x2 ops (Blackwell family-wide PTX) */
typedef unsigned long long u64t;
__device__ __forceinline__ u64t fma2(u64t a, u64t b, u64t c) {
    u64t d;
    asm("fma.rn.f32x2 %0, %1, %2, %3;" : "=l"(d) : "l"(a), "l"(b), "l"(c));
    return d;
}
__device__ __forceinline__ u64t mul2(u64t a, u64t b) {
    u64t d;
    asm("mul.rn.f32x2 %0, %1, %2;" : "=l"(d) : "l"(a), "l"(b));
    return d;
}
__device__ __forceinline__ u64t pack2(float lo, float hi) {
    u64t d;
    asm("mov.b64 %0, {%1, %2};" : "=l"(d) : "f"(lo), "f"(hi));
    return d;
}
__device__ __forceinline__ float2 unpack2(u64t v) {
    float lo, hi;
    asm("mov.b64 {%0, %1}, %2;" : "=f"(lo), "=f"(hi) : "l"(v));
    return make_float2(lo, hi);
}

/* ------------------------------------------------------------------ */
/* 2-term split GEMM (NT): C = Ah*(Bhi + Blo)  (+bias)(+res)(+rope)    */
/* CTA tile 128x256, 8 warps of 64x64 (2x4), BK=64, double-buffered.   */
/* ------------------------------------------------------------------ */
#define PA 16384
#define PB 32768
#define BUFSZ (PA + 2*PB)              /* 81920 */
#define GEMM_SMEM (2*BUFSZ)            /* 163840 */

template<bool ROPE, bool PARTIAL>
__global__ void __launch_bounds__(256, 1) gemm_mma(
    const __half* __restrict__ Ah,
    const __half* __restrict__ Bhi, const __half* __restrict__ Blo,
    const float* __restrict__ bias, const float* __restrict__ res,
    float* __restrict__ C, const float* __restrict__ remb,
    int M, int N, int K) {
    extern __shared__ __align__(128) char smem[];
    uint32_t sb = smem_u32(smem);
    int tid = threadIdx.x, wid = tid >> 5, lane = tid & 31;
    int wm = wid >> 2, wn = wid & 3;
    int bm = blockIdx.y * 128, bn = blockIdx.x * 256;

    int l15 = lane & 15, kg = lane >> 4;
    uint32_t arow = (uint32_t)(wm * 64 + l15);
    uint32_t brow = (uint32_t)(wn * 64 + l15);
    int aswz = (int)(arow & 7), bswz = (int)(brow & 7);

    uint32_t aoff[4], boff[4];
    #pragma unroll
    for (int ks = 0; ks < 4; ks++) {
        int g = ks * 2 + kg;
        aoff[ks] = (uint32_t)((g ^ aswz) * 16);
        boff[ks] = (uint32_t)((g ^ bswz) * 16);
    }
    uint32_t aB0  = sb           + arow * 128u;
    uint32_t bHi0 = sb + PA      + brow * 128u;
    uint32_t bLo0 = sb + PA + PB + brow * 128u;

    float acc[4][8][4];
    #pragma unroll
    for (int i = 0; i < 4; i++)
        #pragma unroll
        for (int j = 0; j < 8; j++)
            #pragma unroll
            for (int e = 0; e < 4; e++) acc[i][j][e] = 0.f;

    int nch = K >> 6;
    int c0 = 0, c1 = nch;
    if (PARTIAL) {
        int z = blockIdx.z;
        c0 = (z * nch) / 3;
        c1 = ((z + 1) * nch) / 3;
    }

    auto load_chunk = [&](uint32_t dst, int ko) {
        #pragma unroll
        for (int j = 0; j < 4; j++) {
            int id = tid + j * 256;
            int row = id >> 3, g = id & 7;
            uint32_t off = (uint32_t)row * 128u + (uint32_t)((g ^ (row & 7)) * 16);
            size_t so = (size_t)(bm + row) * K + ko + g * 8;
            cp16(dst + off, Ah + so);
        }
        #pragma unroll
        for (int j = 0; j < 8; j++) {
            int id = tid + j * 256;
            int row = id >> 3, g = id & 7;
            uint32_t off = (uint32_t)row * 128u + (uint32_t)((g ^ (row & 7)) * 16);
            size_t so = (size_t)(bn + row) * K + ko + g * 8;
            cp16(dst + PA + off,      Bhi + so);
            cp16(dst + PA + PB + off, Blo + so);
        }
    };

    load_chunk(sb, c0 * 64);
    cp_commit();

    for (int c = c0; c < c1; c++) {
        if (c + 1 < c1) {
            load_chunk(sb + (uint32_t)(((c - c0 + 1) & 1) * BUFSZ), (c + 1) * 64);
            cp_commit();
            cp_wait<1>();
        } else {
            cp_wait<0>();
        }
        __syncthreads();

        uint32_t bofs = (uint32_t)(((c - c0) & 1) ? BUFSZ : 0);
        uint32_t a_b  = aB0  + bofs;
        uint32_t b_hi = bHi0 + bofs;
        uint32_t b_lo = bLo0 + bofs;

        #pragma unroll
        for (int ks = 0; ks < 4; ks++) {
            uint32_t afh[4][4], bfh[4][4];
            LDM4(afh, a_b  + aoff[ks]);
            LDM4(bfh, b_hi + boff[ks]);
            #pragma unroll
            for (int mf = 0; mf < 4; mf++)
                #pragma unroll
                for (int nf = 0; nf < 8; nf++)
                    mma16816(acc[mf][nf], afh[mf],
                             bfh[nf >> 1][nf & 1], bfh[nf >> 1][(nf & 1) + 2]);
            {
                uint32_t bfl[4][4];
                LDM4(bfl, b_lo + boff[ks]);
                #pragma unroll
                for (int mf = 0; mf < 4; mf++)
                    #pragma unroll
                    for (int nf = 0; nf < 8; nf++)
                        mma16816(acc[mf][nf], afh[mf],
                                 bfl[nf >> 1][nf & 1], bfl[nf >> 1][(nf & 1) + 2]);
            }
        }
        __syncthreads();
    }

    int r0 = lane >> 2, cb = (lane & 3) * 2;
    if (PARTIAL) {
        float* Cp = C + (size_t)blockIdx.z * M * N;
        #pragma unroll
        for (int mf = 0; mf < 4; mf++)
            #pragma unroll
            for (int nf = 0; nf < 8; nf++) {
                int n0 = bn + wn * 64 + nf * 8 + cb;
                #pragma unroll
                for (int half = 0; half < 2; half++) {
                    int m0 = bm + wm * 64 + mf * 16 + r0 + half * 8;
                    *(float2*)(Cp + (size_t)m0 * N + n0) =
                        make_float2(acc[mf][nf][half * 2], acc[mf][nf][half * 2 + 1]);
                }
            }
        return;
    }
    #pragma unroll
    for (int mf = 0; mf < 4; mf++) {
        #pragma unroll
        for (int nf = 0; nf < 8; nf++) {
            int n0 = bn + wn * 64 + nf * 8 + cb;
            float bz0 = bias ? bias[n0]     : 0.f;
            float bz1 = bias ? bias[n0 + 1] : 0.f;
            #pragma unroll
            for (int half = 0; half < 2; half++) {
                int m0 = bm + wm * 64 + mf * 16 + r0 + half * 8;
                float v0 = acc[mf][nf][half * 2]     + bz0;
                float v1 = acc[mf][nf][half * 2 + 1] + bz1;
                if (ROPE) {
                    if (n0 < 2*DIM) {
                        int pos = m0 & (NTOK - 1);
                        int d   = n0 & (HD - 1);
                        const float* e = remb + pos * (2*HD);
                        float2 sn = *(const float2*)(e + d);
                        float2 cs = *(const float2*)(e + HD + d);
                        float t0 = v0 * cs.x - v1 * sn.x;
                        float t1 = v1 * cs.y + v0 * sn.y;
                        v0 = t0; v1 = t1;
                    }
                }
                size_t idx = (size_t)m0 * N + n0;
                if (res) { v0 += res[idx]; v1 += res[idx + 1]; }
                *(float2*)(C + idx) = make_float2(v0, v1);
            }
        }
    }
}

/* ------------------------------------------------------------------ */
/* reduce3: h += bias + p0 + p1 + p2 (final layer only)                */
/* ------------------------------------------------------------------ */
__global__ void reduce3(float* __restrict__ h, const float* __restrict__ part,
                        const float* __restrict__ bias) {
    int i = blockIdx.x * blockDim.x + threadIdx.x;
    if (i >= TOKENS*DIM/4) return;
    float4 a  = ((const float4*)h)[i];
    float4 p0 = ((const float4*)part)[i];
    float4 p1 = ((const float4*)(part + TOKENS*DIM))[i];
    float4 p2 = ((const float4*)(part + 2*TOKENS*DIM))[i];
    float4 bz = *(const float4*)(bias + (i*4) % DIM);
    a.x += bz.x + ((p0.x + p1.x) + p2.x);
    a.y += bz.y + ((p0.y + p1.y) + p2.y);
    a.z += bz.z + ((p0.z + p1.z) + p2.z);
    a.w += bz.w + ((p0.w + p1.w) + p2.w);
    ((float4*)h)[i] = a;
}

/* ------------------------------------------------------------------ */
/* Single fused fp32 -> (hi, lo) split+pack for ALL weights            */
/* ------------------------------------------------------------------ */
struct CvtArgs {
    const float* src[7];
    __half* hi[7];
    __half* lo[7];
    int lr[7];
    int ltot[7];
    int off[7];
    int cum[8];
};
__device__ __forceinline__ void split2(float a, float b, __half2& h, __half2& l) {
    __half ha = __float2half_rn(a), hb = __float2half_rn(b);
    __half la = __float2half_rn(a - __half2float(ha));
    __half lb = __float2half_rn(b - __half2float(hb));
    h = __halves2half2(ha, hb);
    l = __halves2half2(la, lb);
}
__global__ void cvt_all(CvtArgs a, int total4) {
    int i4 = blockIdx.x * blockDim.x + threadIdx.x;
    if (i4 >= total4) return;
    int s = 0;
    #pragma unroll
    for (int j = 1; j < 7; j++) s += (i4 >= a.cum[j]);
    int i = (i4 - a.cum[s]) * 4;
    int l = i / a.lr[s];
    int rem = i - l * a.lr[s];
    size_t d = (size_t)l * a.ltot[s] + a.off[s] + rem;
    float4 v = *(const float4*)(a.src[s] + i);
    __half2 h0, l0, h1, l1;
    split2(v.x, v.y, h0, l0);
    split2(v.z, v.w, h1, l1);
    ((__half2*)(a.hi[s] + d))[0] = h0; ((__half2*)(a.hi[s] + d))[1] = h1;
    ((__half2*)(a.lo[s] + d))[0] = l0; ((__half2*)(a.lo[s] + d))[1] = l1;
}

/* ------------------------------------------------------------------ */
/* add_pos + bias packing fused                                        */
/* ------------------------------------------------------------------ */
__global__ void add_pos_prep(const float* __restrict__ x,
                             const float* __restrict__ pos,
                             float* __restrict__ h,
                             const float* __restrict__ bq,
                             const float* __restrict__ bv,
                             float* __restrict__ bqkv,
                             const float* __restrict__ bg,
                             const float* __restrict__ bx,
                             float* __restrict__ b1) {
    int idx = blockIdx.x * blockDim.x + threadIdx.x;
    if (idx < TOKENS*DIM) h[idx] = x[idx] + pos[idx % (NTOK*DIM)];
    if (idx < DEPTH*QS) {
        int l = idx / QS, c = idx % QS;
        bqkv[idx] = c < DIM ? bq[l*DIM + c]
                  : (c < 2*DIM ? 0.f : bv[l*DIM + c - 2*DIM]);
    }
    if (idx < DEPTH*GUS) {
        int l = idx / GUS, c = idx % GUS;
        b1[idx] = c < HIDDEN ? bg[l*HIDDEN + c] : bx[l*HIDDEN + c - HIDDEN];
    }
}

/* ------------------------------------------------------------------ */
/* Block reductions (256 threads)                                      */
/* ------------------------------------------------------------------ */
__device__ __forceinline__ float2 block_reduce_2(float s, float s2) {
    __shared__ float red[16];
    #pragma unroll
    for (int o = 16; o > 0; o >>= 1) {
        s  += __shfl_down_sync(0xffffffffu, s,  o);
        s2 += __shfl_down_sync(0xffffffffu, s2, o);
    }
    int w = threadIdx.x >> 5, l = threadIdx.x & 31;
    if (l == 0) { red[w] = s; red[8 + w] = s2; }
    __syncthreads();
    if (threadIdx.x < 32) {
        s  = (l < 8) ? red[l]     : 0.f;
        s2 = (l < 8) ? red[8 + l] : 0.f;
        #pragma unroll
        for (int o = 4; o > 0; o >>= 1) {
            s  += __shfl_down_sync(0xffffffffu, s,  o);
            s2 += __shfl_down_sync(0xffffffffu, s2, o);
        }
        if (l == 0) { red[0] = s; red[1] = s2; }
    }
    __syncthreads();
    return make_float2(red[0], red[1]);
}
__device__ __forceinline__ float block_reduce_max(float m) {
    __shared__ float redm[8];
    #pragma unroll
    for (int o = 16; o > 0; o >>= 1)
        m = fmaxf(m, __shfl_xor_sync(0xffffffffu, m, o));
    int w = threadIdx.x >> 5, l = threadIdx.x & 31;
    if (l == 0) redm[w] = m;
    __syncthreads();
    if (threadIdx.x < 32) {
        m = (l < 8) ? redm[l] : 0.f;
        #pragma unroll
        for (int o = 4; o > 0; o >>= 1)
            m = fmaxf(m, __shfl_xor_sync(0xffffffffu, m, o));
        if (l == 0) redm[0] = m;
    }
    __syncthreads();
    return redm[0];
}

__device__ __forceinline__ uint32_t pack_h2(float a, float b) {
    __half2 h = __floats2half2_rn(a, b);
    return *(uint32_t*)&h;
}

/* ------------------------------------------------------------------ */
/* Fused residual-reduce + LayerNorm over DIM (hi-plane output only)   */
/* ------------------------------------------------------------------ */
__global__ void __launch_bounds__(256) ln_fused(
    float* __restrict__ h, const float* __restrict__ part,
    const float* __restrict__ gbias,
    const float* __restrict__ w, const float* __restrict__ b,
    __half* __restrict__ ohi) {
    int t = blockIdx.x;
    int c4 = threadIdx.x;
    size_t i4 = (size_t)t * (DIM/4) + c4;
    float4 v = make_float4(0.f, 0.f, 0.f, 0.f);
    if (c4 < DIM/4) {
        v = ((const float4*)h)[i4];
        if (part) {
            float4 p0 = ((const float4*)part)[i4];
            float4 p1 = ((const float4*)(part + TOKENS*DIM))[i4];
            float4 p2 = ((const float4*)(part + 2*TOKENS*DIM))[i4];
            float4 bz = ((const float4*)gbias)[c4];
            v.x += bz.x + ((p0.x + p1.x) + p2.x);
            v.y += bz.y + ((p0.y + p1.y) + p2.y);
            v.z += bz.z + ((p0.z + p1.z) + p2.z);
            v.w += bz.w + ((p0.w + p1.w) + p2.w);
            ((float4*)h)[i4] = v;
        }
    }
    float s  = v.x + v.y + v.z + v.w;
    float s2 = v.x*v.x + v.y*v.y + v.z*v.z + v.w*v.w;
    float2 r = block_reduce_2(s, s2);
    float mean = r.x / DIM;
    float var  = r.y / DIM - mean * mean;
    float inv  = rsqrtf(var + EPSF);
    if (c4 < DIM/4) {
        float4 wv = ((const float4*)w)[c4];
        float4 bv = ((const float4*)b)[c4];
        float y0 = (v.x - mean) * inv * wv.x + bv.x;
        float y1 = (v.y - mean) * inv * wv.y + bv.y;
        float y2 = (v.z - mean) * inv * wv.z + bv.z;
        float y3 = (v.w - mean) * inv * wv.w + bv.w;
        ((uint2*)ohi)[i4] = make_uint2(pack_h2(y0, y1), pack_h2(y2, y3));
    }
}

/* ------------------------------------------------------------------ */
/* silu(g)*u then LN over HIDDEN (hi-plane output only)                */
/* ------------------------------------------------------------------ */
__global__ void __launch_bounds__(256) mlp_act_ln_kernel(
    const float* __restrict__ gu,
    const float* __restrict__ w, const float* __restrict__ b,
    __half* __restrict__ ohi) {
    int t = blockIdx.x;
    const float* gr = gu + (size_t)t * GUS;
    const float* ur = gr + HIDDEN;
    float a[8];
    float s = 0.f, s2 = 0.f;
    #pragma unroll
    for (int j = 0; j < 2; j++) {
        int c4 = threadIdx.x + j * 256;
        float4 gv = ((const float4*)gr)[c4];
        float4 uv = ((const float4*)ur)[c4];
        float* aj = a + j * 4;
        aj[0] = gv.x / (1.f + __expf(-gv.x)) * uv.x;
        aj[1] = gv.y / (1.f + __expf(-gv.y)) * uv.y;
        aj[2] = gv.z / (1.f + __expf(-gv.z)) * uv.z;
        aj[3] = gv.w / (1.f + __expf(-gv.w)) * uv.w;
        s  += aj[0] + aj[1] + aj[2] + aj[3];
        s2 += aj[0]*aj[0] + aj[1]*aj[1] + aj[2]*aj[2] + aj[3]*aj[3];
    }
    float2 r = block_reduce_2(s, s2);
    float mean = r.x / HIDDEN;
    float var  = r.y / HIDDEN - mean * mean;
    float inv  = rsqrtf(var + EPSF);
    #pragma unroll
    for (int j = 0; j < 2; j++) {
        int c4 = threadIdx.x + j * 256;
        float4 wv = ((const float4*)w)[c4];
        float4 bv = ((const float4*)b)[c4];
        float* aj = a + j * 4;
        float y0 = (aj[0] - mean) * inv * wv.x + bv.x;
        float y1 = (aj[1] - mean) * inv * wv.y + bv.y;
        float y2 = (aj[2] - mean) * inv * wv.z + bv.z;
        float y3 = (aj[3] - mean) * inv * wv.w + bv.w;
        ((uint2*)ohi)[(size_t)t * (HIDDEN/4) + c4] =
            make_uint2(pack_h2(y0, y1), pack_h2(y2, y3));
    }
}

/* ------------------------------------------------------------------ */
/* Attention: 2 queries/thread, quad-strided slices, static max bound, */
/* packed f32x2 FMA inner loop.                                        */
/* ------------------------------------------------------------------ */
#define KVT 128
#define ATTN_SMEM (2*KVT*HD*4)    /* 65536 */
__global__ void __launch_bounds__(256) attn_kernel(
    const float* __restrict__ qkv, __half* __restrict__ ohi) {
    extern __shared__ float sm[];
    float* Ks = sm;
    float* Vs = sm + KVT * HD;
    int blk = blockIdx.x;
    int half_blk = blk & 1;
    int bh = blk >> 1;
    int b  = bh / HEADS, h = bh % HEADS;
    size_t base = (size_t)(b * NTOK) * QS + h * HD;
    int tid = threadIdx.x;
    int g  = tid & 3;
    int qb = tid >> 2;
    const float scale = 0.125f;

    float km2 = 0.f;
    {
        const float* kp = qkv + base + (size_t)tid * QS + DIM;
        #pragma unroll 4
        for (int c4 = 0; c4 < 16; c4++) {
            float4 t = *(const float4*)(kp + c4 * 4);
            km2 += t.x*t.x + t.y*t.y + t.z*t.z + t.w*t.w;
        }
    }
    float kmax = sqrtf(block_reduce_max(km2));

    u64t q2[2][8], acc2[2][8];
    float lrun[2], Mq[2];
    const u64t scale2 = pack2(scale, scale);
    #pragma unroll
    for (int r = 0; r < 2; r++) {
        int q = half_blk * 128 + qb + 64 * r;
        const float* qp = qkv + base + (size_t)q * QS;
        float qn2 = 0.f;
        #pragma unroll
        for (int k4 = 0; k4 < 4; k4++) {
            ulonglong2 v = *(const ulonglong2*)(qp + k4 * 16 + g * 4);
            q2[r][k4*2]   = mul2(v.x, scale2);
            q2[r][k4*2+1] = mul2(v.y, scale2);
            float2 a = unpack2(q2[r][k4*2]),  bb = unpack2(q2[r][k4*2+1]);
            qn2 += a.x*a.x + a.y*a.y + bb.x*bb.x + bb.y*bb.y;
        }
        qn2 += __shfl_xor_sync(0xffffffffu, qn2, 1);
        qn2 += __shfl_xor_sync(0xffffffffu, qn2, 2);
        Mq[r] = sqrtf(qn2) * kmax;
        lrun[r] = 0.f;
        #pragma unroll
        for (int d = 0; d < 8; d++) acc2[r][d] = 0ull;
    }

    for (int tkv = 0; tkv < NTOK / KVT; tkv++) {
        for (int i4 = tid; i4 < KVT * HD / 4; i4 += 256) {
            int row = i4 >> 4, c4 = i4 & 15;
            size_t src = base + (size_t)(tkv * KVT + row) * QS;
            ((float4*)Ks)[i4] = *(const float4*)(qkv + src + DIM   + c4 * 4);
            ((float4*)Vs)[i4] = *(const float4*)(qkv + src + 2*DIM + c4 * 4);
        }
        __syncthreads();

        for (int j = 0; j < KVT; j++) {
            u64t k2[8], v2[8];
            const float* kr = Ks + j * HD;
            const float* vr = Vs + j * HD;
            #pragma unroll
            for (int k4 = 0; k4 < 4; k4++) {
                ulonglong2 t = *(const ulonglong2*)(kr + k4 * 16 + g * 4);
                k2[k4*2] = t.x; k2[k4*2+1] = t.y;
                ulonglong2 u = *(const ulonglong2*)(vr + k4 * 16 + g * 4);
                v2[k4*2] = u.x; v2[k4*2+1] = u.y;
            }
            #pragma unroll
            for (int r = 0; r < 2; r++) {
                u64t d2 = 0ull;
                #pragma unroll
                for (int d = 0; d < 8; d++) d2 = fma2(q2[r][d], k2[d], d2);
                float2 dp = unpack2(d2);
                float s = dp.x + dp.y;
                s += __shfl_xor_sync(0xffffffffu, s, 1);
                s += __shfl_xor_sync(0xffffffffu, s, 2);
                float p = __expf(s - Mq[r]);
                lrun[r] += p;
                u64t p2 = pack2(p, p);
                #pragma unroll
                for (int d = 0; d < 8; d++)
                    acc2[r][d] = fma2(p2, v2[d], acc2[r][d]);
            }
        }
        __syncthreads();
    }

    #pragma unroll
    for (int r = 0; r < 2; r++) {
        float inv = 1.f / lrun[r];
        int q = half_blk * 128 + qb + 64 * r;
        size_t ob = (size_t)(b * NTOK + q) * DIM + h * HD;
        #pragma unroll
        for (int k4 = 0; k4 < 4; k4++) {
            float2 a = unpack2(acc2[r][k4*2]);
            float2 bb = unpack2(acc2[r][k4*2+1]);
            float y0 = a.x * inv,  y1 = a.y * inv;
            float y2 = bb.x * inv, y3 = bb.y * inv;
            *(uint2*)(ohi + ob + k4 * 16 + g * 4) =
                make_uint2(pack_h2(y0, y1), pack_h2(y2, y3));
        }
    }
}

/* ------------------------------------------------------------------ */
/* Launch                                                              */
/* ------------------------------------------------------------------ */
extern "C" void kernel_launch(void* const* d_in, const int* in_sizes, int n_in,
                              void* d_out, int out_size) {
    const float* x      = (const float*)d_in[0];
    const float* pos    = (const float*)d_in[1];
    const float* rope   = (const float*)d_in[2];
    const float* ln1_w  = (const float*)d_in[3];
    const float* ln1_b  = (const float*)d_in[4];
    const float* wq     = (const float*)d_in[5];
    const float* bq     = (const float*)d_in[6];
    const float* wk     = (const float*)d_in[7];
    const float* wv     = (const float*)d_in[8];
    const float* bv     = (const float*)d_in[9];
    const float* wo     = (const float*)d_in[10];
    const float* bo     = (const float*)d_in[11];
    const float* ln2_w  = (const float*)d_in[12];
    const float* ln2_b  = (const float*)d_in[13];
    const float* w1g    = (const float*)d_in[14];
    const float* b1g    = (const float*)d_in[15];
    const float* w1x    = (const float*)d_in[16];
    const float* b1x    = (const float*)d_in[17];
    const float* lnm_w  = (const float*)d_in[18];
    const float* lnm_b  = (const float*)d_in[19];
    const float* w2     = (const float*)d_in[20];
    const float* b2     = (const float*)d_in[21];
    float* h = (float*)d_out;

    float *qkv, *gu, *bqkv, *b1, *part;
    __half *yhh, *ohh, *mhh;
    __half *wqkvh, *wqkvl, *woh, *wol, *w1h, *w1l, *w2h, *w2l;
    cudaGetSymbolAddress((void**)&qkv,   g_qkv);
    cudaGetSymbolAddress((void**)&gu,    g_gu);
    cudaGetSymbolAddress((void**)&part,  g_part);
    cudaGetSymbolAddress((void**)&bqkv,  g_bqkv);
    cudaGetSymbolAddress((void**)&b1,    g_b1);
    cudaGetSymbolAddress((void**)&yhh,   g_yh_hi);
    cudaGetSymbolAddress((void**)&ohh,   g_oh_hi);
    cudaGetSymbolAddress((void**)&mhh,   g_mh_hi);
    cudaGetSymbolAddress((void**)&wqkvh, g_wqkv_hi);
    cudaGetSymbolAddress((void**)&wqkvl, g_wqkv_lo);
    cudaGetSymbolAddress((void**)&woh,   g_wo_hi);
    cudaGetSymbolAddress((void**)&wol,   g_wo_lo);
    cudaGetSymbolAddress((void**)&w1h,   g_w1_hi);
    cudaGetSymbolAddress((void**)&w1l,   g_w1_lo);
    cudaGetSymbolAddress((void**)&w2h,   g_w2_hi);
    cudaGetSymbolAddress((void**)&w2l,   g_w2_lo);

    cudaFuncSetAttribute((const void*)gemm_mma<true,false>,
                         cudaFuncAttributeMaxDynamicSharedMemorySize, GEMM_SMEM);
    cudaFuncSetAttribute((const void*)gemm_mma<false,false>,
                         cudaFuncAttributeMaxDynamicSharedMemorySize, GEMM_SMEM);
    cudaFuncSetAttribute((const void*)gemm_mma<false,true>,
                         cudaFuncAttributeMaxDynamicSharedMemorySize, GEMM_SMEM);
    cudaFuncSetAttribute((const void*)attn_kernel,
                         cudaFuncAttributeMaxDynamicSharedMemorySize, ATTN_SMEM);

    /* ---- [1] fused weight split + pack ---- */
    {
        const int nD = DIM*DIM, nH = HIDDEN*DIM;
        CvtArgs a;
        const float* srcs[7] = { wq, wk, wv, wo, w1g, w1x, w2 };
        __half* his[7] = { wqkvh, wqkvh, wqkvh, woh, w1h, w1h, w2h };
        __half* los[7] = { wqkvl, wqkvl, wqkvl, wol, w1l, w1l, w2l };
        int lrs[7]   = { nD, nD, nD, nD, nH, nH, nH };
        int ltots[7] = { QS*DIM, QS*DIM, QS*DIM, nD, GUS*DIM, GUS*DIM, nH };
        int offs[7]  = { 0, nD, 2*nD, 0, 0, nH, 0 };
        int cum = 0;
        for (int s = 0; s < 7; s++) {
            a.src[s] = srcs[s]; a.hi[s] = his[s]; a.lo[s] = los[s];
            a.lr[s] = lrs[s]; a.ltot[s] = ltots[s]; a.off[s] = offs[s];
            a.cum[s] = cum;
            cum += DEPTH * lrs[s] / 4;
        }
        a.cum[7] = cum;
        cvt_all<<<(cum + 255)/256, 256>>>(a, cum);
    }
    /* ---- [2] pos-embed add + bias packing ---- */
    add_pos_prep<<<(TOKENS*DIM + 255)/256, 256>>>(x, pos, h, bq, bv, bqkv,
                                                  b1g, b1x, b1);

    dim3 gQKV(QS/256,  TOKENS/128);      /* (9, 32)    */
    dim3 gMLP(GUS/256, TOKENS/128);      /* (16, 32)   */
    dim3 gSK (DIM/256, TOKENS/128, 3);   /* (3, 32, 3) */
    const int RED = (TOKENS*DIM/4 + 255)/256;

    for (int l = 0; l < DEPTH; l++) {
        size_t oqkv = (size_t)l * QS * DIM;
        size_t owo  = (size_t)l * DIM * DIM;
        size_t ow1  = (size_t)l * GUS * DIM;
        size_t ow2  = (size_t)l * DIM * HIDDEN;

        /* ---- attention (ln1 fused with previous layer's W2 reduce) ---- */
        ln_fused<<<TOKENS, 256>>>(h,
            l == 0 ? nullptr : part,
            l == 0 ? nullptr : b2 + (l-1)*DIM,
            ln1_w + l*DIM, ln1_b + l*DIM, yhh);
        gemm_mma<true,false><<<gQKV, 256, GEMM_SMEM>>>(
            yhh, wqkvh + oqkv, wqkvl + oqkv,
            bqkv + l*QS, nullptr, qkv, rope, TOKENS, QS, DIM);
        attn_kernel<<<BATCH*HEADS*2, 256, ATTN_SMEM>>>(qkv, ohh);
        gemm_mma<false,true><<<gSK, 256, GEMM_SMEM>>>(
            ohh, woh + owo, wol + owo,
            nullptr, nullptr, part, nullptr, TOKENS, DIM, DIM);

        /* ---- SwiGLU MLP (ln2 fused with O-proj reduce) ---- */
        ln_fused<<<TOKENS, 256>>>(h, part, bo + l*DIM,
            ln2_w + l*DIM, ln2_b + l*DIM, yhh);
        gemm_mma<false,false><<<gMLP, 256, GEMM_SMEM>>>(
            yhh, w1h + ow1, w1l + ow1,
            b1 + l*GUS, nullptr, gu, nullptr, TOKENS, GUS, DIM);
        mlp_act_ln_kernel<<<TOKENS, 256>>>(gu, lnm_w + l*HIDDEN, lnm_b + l*HIDDEN, mhh);
        gemm_mma<false,true><<<gSK, 256, GEMM_SMEM>>>(
            mhh, w2h + ow2, w2l + ow2,
            nullptr, nullptr, part, nullptr, TOKENS, DIM, HIDDEN);
    }
    /* final residual reduce */
    reduce3<<<RED, 256>>>(h, part, b2 + (DEPTH-1)*DIM);
}